// round 10
// baseline (speedup 1.0000x reference)
#include <cuda_runtime.h>
#include <cuda_bf16.h>
#include <cstdint>

#define N_NODES 50000
#define N_EDGES 800000
#define N_GRAPHS 1024
#define H 128
#define H2 256
#define L 5
#define NT (N_EDGES / 128)     // 6250 edge tiles
#define CV_GRID 148

// ---------------- scratch (__device__ globals: allowed) ----------------
__device__ float          g_x[N_NODES * H];
__device__ __nv_bfloat16  g_x_bf[N_NODES * H];
__device__ __nv_bfloat16  g_e_bf[(size_t)N_EDGES * H];
__device__ float          g_p[(size_t)N_NODES * H2];   // P = x @ W1_top + b1
__device__ float          g_aggr[N_NODES * H];
__device__ float          g_cnt[N_NODES];
__device__ float          g_crystal[N_GRAPHS * H];
__device__ float          g_gcnt[N_GRAPHS];
__device__ __nv_bfloat16  g_w1[L * H2 * H2];
__device__ __nv_bfloat16  g_w2[L * H2 * H];

__device__ __forceinline__ float silu(float x) { return x / (1.f + expf(-x)); }

// ---------------- PTX helpers ----------------
__device__ __forceinline__ void ldsm_x4(uint32_t r[4], const void* p) {
    uint32_t a = (uint32_t)__cvta_generic_to_shared(p);
    asm volatile("ldmatrix.sync.aligned.m8n8.x4.shared.b16 {%0,%1,%2,%3},[%4];\n"
                 : "=r"(r[0]), "=r"(r[1]), "=r"(r[2]), "=r"(r[3]) : "r"(a));
}
__device__ __forceinline__ void ldsm_x4t(uint32_t r[4], const void* p) {
    uint32_t a = (uint32_t)__cvta_generic_to_shared(p);
    asm volatile("ldmatrix.sync.aligned.m8n8.x4.trans.shared.b16 {%0,%1,%2,%3},[%4];\n"
                 : "=r"(r[0]), "=r"(r[1]), "=r"(r[2]), "=r"(r[3]) : "r"(a));
}
__device__ __forceinline__ void mma_bf16(float d[4], const uint32_t a[4], uint32_t b0, uint32_t b1) {
    asm volatile(
        "mma.sync.aligned.m16n8k16.row.col.f32.bf16.bf16.f32 "
        "{%0,%1,%2,%3},{%4,%5,%6,%7},{%8,%9},{%0,%1,%2,%3};\n"
        : "+f"(d[0]), "+f"(d[1]), "+f"(d[2]), "+f"(d[3])
        : "r"(a[0]), "r"(a[1]), "r"(a[2]), "r"(a[3]), "r"(b0), "r"(b1));
}
__device__ __forceinline__ void red_v2(float* p, float a, float b) {
    asm volatile("red.global.add.v2.f32 [%0], {%1,%2};\n" :: "l"(p), "f"(a), "f"(b) : "memory");
}
__device__ __forceinline__ void cp16(void* s, const void* g) {
    uint32_t sa = (uint32_t)__cvta_generic_to_shared(s);
    asm volatile("cp.async.cg.shared.global [%0],[%1],16;\n" :: "r"(sa), "l"(g));
}
#define CP_COMMIT() asm volatile("cp.async.commit_group;\n")
#define CP_WAIT(n)  asm volatile("cp.async.wait_group %0;\n" :: "n"(n))

// XOR swizzle within a row (applies to byte offset inside the row).
// For any power-of-2 row stride >= 128B this makes 8 consecutive rows'
// same-column 16B chunks hit distinct banks (conflict-free ldmatrix).
#define SWZ(r, inrow) ((inrow) ^ (((r) & 7) << 4))

// ---------------- small kernels ----------------
__global__ void zero_kernel() {
    int i = blockIdx.x * 256 + threadIdx.x;
    if (i < N_NODES * H)  g_aggr[i] = 0.f;
    if (i < N_NODES)      g_cnt[i] = 0.f;
    if (i < N_GRAPHS * H) g_crystal[i] = 0.f;
    if (i < N_GRAPHS)     g_gcnt[i] = 0.f;
}

__global__ void prep_w(const float* w1, const float* w2) {
    int i = blockIdx.x * 256 + threadIdx.x;
    if (i < L * H2 * H2) g_w1[i] = __float2bfloat16(w1[i]);
    if (i < L * H2 * H)  g_w2[i] = __float2bfloat16(w2[i]);
}

__device__ __forceinline__ void ln_stats(float v, float& mean, float& var) {
    __shared__ float red[8];
    int lane = threadIdx.x & 31, wid = threadIdx.x >> 5;
    float s = v;
    #pragma unroll
    for (int o = 16; o; o >>= 1) s += __shfl_xor_sync(0xffffffffu, s, o);
    if (!lane) red[wid] = s;
    __syncthreads();
    mean = (red[0] + red[1] + red[2] + red[3]) * (1.f / H);
    float d = v - mean, sq = d * d;
    #pragma unroll
    for (int o = 16; o; o >>= 1) sq += __shfl_xor_sync(0xffffffffu, sq, o);
    if (!lane) red[4 + wid] = sq;
    __syncthreads();
    var = (red[4] + red[5] + red[6] + red[7]) * (1.f / H);
}

__global__ __launch_bounds__(H) void node_embed(const float* atom, const float* w,
                                                const float* b, const float* lg, const float* lb) {
    int n = blockIdx.x, c = threadIdx.x;
    float a0 = atom[n * 4 + 0], a1 = atom[n * 4 + 1], a2 = atom[n * 4 + 2], a3 = atom[n * 4 + 3];
    float v = b[c] + a0 * w[c] + a1 * w[H + c] + a2 * w[2 * H + c] + a3 * w[3 * H + c];
    float mean, var;
    ln_stats(v, mean, var);
    float y = (v - mean) * rsqrtf(var + 1e-5f) * lg[c] + lb[c];
    y = silu(y);
    g_x[n * H + c] = y;
    g_x_bf[n * H + c] = __float2bfloat16(y);
}

__global__ __launch_bounds__(64) void edge_embed(const float* nf, const float* w, const float* b) {
    __shared__ float nfs[128 * 42];
    int t = threadIdx.x;
    int e0 = blockIdx.x * 128;
    float wr0[41], wr1[41];
    #pragma unroll
    for (int k = 0; k < 41; k++) { wr0[k] = w[k * H + 2 * t]; wr1[k] = w[k * H + 2 * t + 1]; }
    float b0 = b[2 * t], b1 = b[2 * t + 1];
    for (int i = t; i < 128 * 41; i += 64)
        nfs[(i / 41) * 42 + (i % 41)] = nf[(size_t)e0 * 41 + i];
    __syncthreads();
    for (int e = 0; e < 128; e++) {
        float a0 = b0, a1 = b1;
        #pragma unroll
        for (int k = 0; k < 41; k++) {
            float v = nfs[e * 42 + k];
            a0 += v * wr0[k];
            a1 += v * wr1[k];
        }
        __nv_bfloat162 o;
        o.x = __float2bfloat16(silu(a0));
        o.y = __float2bfloat16(silu(a1));
        *(__nv_bfloat162*)(g_e_bf + (size_t)(e0 + e) * H + 2 * t) = o;
    }
}

__global__ void cnt_kernel(const int* nbr) {
    int i = blockIdx.x * 256 + threadIdx.x;
    if (i < N_EDGES) atomicAdd(&g_cnt[nbr[2 * i + 1]], 1.f);
}

extern __shared__ char smem_raw[];

// ================= node GEMM: P = x_bf @ W1_top + b1 (fp32 out) =============
#define PAS_LD 136
#define PBS_LD 136
#define P_SMEM (128 * PAS_LD * 2 + 2 * 64 * PBS_LD * 2)

__global__ __launch_bounds__(256, 2) void conv_p_kernel(const float* cb1, int layer) {
    __nv_bfloat16* As = (__nv_bfloat16*)smem_raw;
    __nv_bfloat16* Bs = As + 128 * PAS_LD;
    const int tid = threadIdx.x;
    const int n0 = blockIdx.x * 128, nh = blockIdx.y;
    const __nv_bfloat16* W = g_w1 + (size_t)layer * H2 * H2;   // rows 0..127 = W1_top
    const int lane = tid & 31, warp = tid >> 5;
    const int wm = warp & 3, wn = warp >> 2;   // 4 x 2 warps: M32 x N64

    #pragma unroll
    for (int i = 0; i < 8; i++) {
        int idx = i * 256 + tid;
        int row = idx >> 4, col = (idx & 15) << 3;
        int nr = n0 + row; if (nr >= N_NODES) nr = 0;
        cp16(As + row * PAS_LD + col, g_x_bf + (size_t)nr * H + col);
    }
    CP_COMMIT();
    #pragma unroll
    for (int kt = 0; kt < 2; kt++) {
        #pragma unroll
        for (int i = 0; i < 4; i++) {
            int idx = i * 256 + tid;
            int row = idx >> 4, col = (idx & 15) << 3;
            cp16(Bs + kt * 64 * PBS_LD + row * PBS_LD + col,
                 W + (size_t)(kt * 64 + row) * H2 + nh * 128 + col);
        }
        CP_COMMIT();
    }

    float acc[2][8][4];
    #pragma unroll
    for (int mt = 0; mt < 2; mt++)
        #pragma unroll
        for (int nt = 0; nt < 8; nt++)
            #pragma unroll
            for (int j = 0; j < 4; j++) acc[mt][nt][j] = 0.f;

    #pragma unroll
    for (int kt = 0; kt < 2; kt++) {
        if (kt == 0) CP_WAIT(1); else CP_WAIT(0);
        __syncthreads();
        const __nv_bfloat16* Bt = Bs + kt * 64 * PBS_LD;
        #pragma unroll
        for (int k16 = 0; k16 < 4; k16++) {
            uint32_t af[2][4];
            #pragma unroll
            for (int mt = 0; mt < 2; mt++)
                ldsm_x4(af[mt], As + (wm * 32 + mt * 16 + (lane & 15)) * PAS_LD
                                  + kt * 64 + k16 * 16 + ((lane >> 4) << 3));
            uint32_t bfr[4][4];
            #pragma unroll
            for (int q = 0; q < 4; q++)
                ldsm_x4t(bfr[q], Bt + (k16 * 16 + (lane & 15)) * PBS_LD
                                   + wn * 64 + q * 16 + ((lane >> 4) << 3));
            #pragma unroll
            for (int mt = 0; mt < 2; mt++)
                #pragma unroll
                for (int nt = 0; nt < 8; nt++)
                    mma_bf16(acc[mt][nt], af[mt], bfr[nt >> 1][(nt & 1) * 2], bfr[nt >> 1][(nt & 1) * 2 + 1]);
        }
    }

    const float* bp = cb1 + layer * H2 + nh * 128;
    #pragma unroll
    for (int mt = 0; mt < 2; mt++) {
        int r = wm * 32 + mt * 16 + (lane >> 2);
        #pragma unroll
        for (int nt = 0; nt < 8; nt++) {
            int col = wn * 64 + nt * 8 + (lane & 3) * 2;
            float b0 = bp[col], b1v = bp[col + 1];
            if (n0 + r < N_NODES) {
                float2 v = {acc[mt][nt][0] + b0, acc[mt][nt][1] + b1v};
                *(float2*)(g_p + (size_t)(n0 + r) * H2 + nh * 128 + col) = v;
            }
            if (n0 + r + 8 < N_NODES) {
                float2 v = {acc[mt][nt][2] + b0, acc[mt][nt][3] + b1v};
                *(float2*)(g_p + (size_t)(n0 + r + 8) * H2 + nh * 128 + col) = v;
            }
        }
    }
}

// ================= persistent fused edge conv =================
// 148 CTAs x 512 threads (16 warps). Weights for the layer live in smem for
// the whole kernel; each CTA loops over edge tiles of 128 edges.
// Phase A: Q = e @ W1_bot; h1 = silu(Q + P[src]); half0 -> Hs, half1 -> Es(cur).
// Phase B: aggr[dst] += silu(h1 @ W2 + b2).
// smem (bytes): W1s[128x512] 65536 | W2s[256x256] 65536 | Es 2x[128x256] 65536
//               | Hs[128x256] 32768 | idx 1024  => 230400
#define SM_W1  0
#define SM_W2  65536
#define SM_E0  131072
#define SM_E1  163840
#define SM_HS  196608
#define SM_IDX 229376
#define CV_SMEM 230400

__global__ __launch_bounds__(512, 1) void conv_edge(const int* nbr, const float* cb2, int layer) {
    char* W1s = smem_raw + SM_W1;   // 128 K-rows x 256 N-cols, 512B/row, swizzled
    char* W2s = smem_raw + SM_W2;   // 256 K-rows x 128 N-cols, 256B/row, swizzled
    char* Esb[2] = { smem_raw + SM_E0, smem_raw + SM_E1 };  // 128 x 128, 256B/row, swizzled
    char* Hs  = smem_raw + SM_HS;
    int* srcs = (int*)(smem_raw + SM_IDX);
    int* dsts = srcs + 128;

    const int tid = threadIdx.x;
    const int lane = tid & 31, warp = tid >> 5;
    const int wm = warp & 3, wn = warp >> 2;   // 4 x 4 warps: M32 x N32
    const __nv_bfloat16* W1g = g_w1 + (size_t)layer * H2 * H2;   // rows 128..255 = W1_bot
    const __nv_bfloat16* W2g = g_w2 + (size_t)layer * H2 * H;

    // ---- load resident weights (once) ----
    #pragma unroll
    for (int i = 0; i < 8; i++) {          // W1_bot: 4096 chunks
        int idx = i * 512 + tid;
        int r = idx >> 5, c16 = idx & 31;
        cp16(W1s + r * 512 + SWZ(r, c16 * 16), W1g + (size_t)(128 + r) * H2 + c16 * 8);
    }
    #pragma unroll
    for (int i = 0; i < 8; i++) {          // W2: 4096 chunks
        int idx = i * 512 + tid;
        int r = idx >> 4, c16 = idx & 15;
        cp16(W2s + r * 256 + SWZ(r, c16 * 16), W2g + (size_t)r * H + c16 * 8);
    }
    CP_COMMIT();

    // ---- prefetch first tile's e panel ----
    int tile0 = blockIdx.x;
    if (tile0 < NT) {
        #pragma unroll
        for (int i = 0; i < 4; i++) {
            int idx = i * 512 + tid;
            int r = idx >> 4, c16 = idx & 15;
            cp16(Esb[0] + r * 256 + SWZ(r, c16 * 16),
                 g_e_bf + (size_t)(tile0 * 128 + r) * H + c16 * 8);
        }
    }
    CP_COMMIT();

    const float* bp2 = cb2 + layer * H;
    int buf = 0;

    for (int tile = tile0; tile < NT; tile += CV_GRID) {
        // prefetch next tile's e panel into the other buffer
        int ntile = tile + CV_GRID;
        if (ntile < NT) {
            char* Ed = Esb[buf ^ 1];
            #pragma unroll
            for (int i = 0; i < 4; i++) {
                int idx = i * 512 + tid;
                int r = idx >> 4, c16 = idx & 15;
                cp16(Ed + r * 256 + SWZ(r, c16 * 16),
                     g_e_bf + (size_t)(ntile * 128 + r) * H + c16 * 8);
            }
        }
        CP_COMMIT();   // always commit (empty group ok) to keep wait arithmetic

        if (tid < 128) {
            int2 pr = ((const int2*)nbr)[tile * 128 + tid];
            srcs[tid] = pr.x;
            dsts[tid] = pr.y;
        }
        CP_WAIT(1);        // current tile's e panel (and weights) complete
        __syncthreads();   // sync 1

        char* EsC = Esb[buf];

        // -------- Phase A: two N-halves --------
        #pragma unroll
        for (int half = 0; half < 2; half++) {
            float acc_a[2][4][4];
            #pragma unroll
            for (int mt = 0; mt < 2; mt++)
                #pragma unroll
                for (int nt = 0; nt < 4; nt++)
                    #pragma unroll
                    for (int j = 0; j < 4; j++) acc_a[mt][nt][j] = 0.f;

            #pragma unroll
            for (int k16 = 0; k16 < 8; k16++) {
                uint32_t af[2][4];
                #pragma unroll
                for (int mt = 0; mt < 2; mt++) {
                    int rr = wm * 32 + mt * 16 + (lane & 15);
                    int kin = (k16 * 16 + ((lane >> 4) << 3)) * 2;
                    ldsm_x4(af[mt], EsC + rr * 256 + SWZ(rr, kin));
                }
                uint32_t bfr[2][4];
                #pragma unroll
                for (int q = 0; q < 2; q++) {
                    int rk = k16 * 16 + (lane & 15);
                    int cin = (half * 128 + wn * 32 + q * 16 + ((lane >> 4) << 3)) * 2;
                    ldsm_x4t(bfr[q], W1s + rk * 512 + SWZ(rk, cin));
                }
                #pragma unroll
                for (int mt = 0; mt < 2; mt++)
                    #pragma unroll
                    for (int nt = 0; nt < 4; nt++)
                        mma_bf16(acc_a[mt][nt], af[mt], bfr[nt >> 1][(nt & 1) * 2], bfr[nt >> 1][(nt & 1) * 2 + 1]);
            }

            if (half == 1) __syncthreads();   // all warps done reading EsC before overwrite
            char* Ht = half ? EsC : Hs;
            #pragma unroll
            for (int mt = 0; mt < 2; mt++) {
                int rloc = wm * 32 + mt * 16 + (lane >> 2);
                int s0 = srcs[rloc], s1 = srcs[rloc + 8];
                #pragma unroll
                for (int nt = 0; nt < 4; nt++) {
                    int lcol = wn * 32 + nt * 8 + (lane & 3) * 2;
                    int gcol = half * 128 + lcol;
                    float2 p0 = *(const float2*)(g_p + (size_t)s0 * H2 + gcol);
                    float2 p1 = *(const float2*)(g_p + (size_t)s1 * H2 + gcol);
                    __nv_bfloat162 v01, v23;
                    v01.x = __float2bfloat16(silu(acc_a[mt][nt][0] + p0.x));
                    v01.y = __float2bfloat16(silu(acc_a[mt][nt][1] + p0.y));
                    v23.x = __float2bfloat16(silu(acc_a[mt][nt][2] + p1.x));
                    v23.y = __float2bfloat16(silu(acc_a[mt][nt][3] + p1.y));
                    *(__nv_bfloat162*)(Ht + (size_t)rloc * 256 + SWZ(rloc, lcol * 2)) = v01;
                    *(__nv_bfloat162*)(Ht + (size_t)(rloc + 8) * 256 + SWZ(rloc + 8, lcol * 2)) = v23;
                }
            }
        }
        __syncthreads();   // sync 2: h1 fully visible

        // -------- Phase B: K=256 over Hs | EsC --------
        float acc_b[2][4][4];
        #pragma unroll
        for (int mt = 0; mt < 2; mt++)
            #pragma unroll
            for (int nt = 0; nt < 4; nt++)
                #pragma unroll
                for (int j = 0; j < 4; j++) acc_b[mt][nt][j] = 0.f;

        #pragma unroll
        for (int k16 = 0; k16 < 16; k16++) {
            const char* Apan = (k16 < 8) ? Hs : EsC;     // folds at compile time
            const int klocal = (k16 < 8) ? k16 : (k16 - 8);
            uint32_t af[2][4];
            #pragma unroll
            for (int mt = 0; mt < 2; mt++) {
                int rr = wm * 32 + mt * 16 + (lane & 15);
                int kin = (klocal * 16 + ((lane >> 4) << 3)) * 2;
                ldsm_x4(af[mt], Apan + rr * 256 + SWZ(rr, kin));
            }
            uint32_t bfr[2][4];
            #pragma unroll
            for (int q = 0; q < 2; q++) {
                int rk = k16 * 16 + (lane & 15);
                int cin = (wn * 32 + q * 16 + ((lane >> 4) << 3)) * 2;
                ldsm_x4t(bfr[q], W2s + rk * 256 + SWZ(rk, cin));
            }
            #pragma unroll
            for (int mt = 0; mt < 2; mt++)
                #pragma unroll
                for (int nt = 0; nt < 4; nt++)
                    mma_bf16(acc_b[mt][nt], af[mt], bfr[nt >> 1][(nt & 1) * 2], bfr[nt >> 1][(nt & 1) * 2 + 1]);
        }

        // scatter epilogue
        #pragma unroll
        for (int mt = 0; mt < 2; mt++) {
            int rloc = wm * 32 + mt * 16 + (lane >> 2);
            int d0 = dsts[rloc], d1 = dsts[rloc + 8];
            #pragma unroll
            for (int nt = 0; nt < 4; nt++) {
                int col = wn * 32 + nt * 8 + (lane & 3) * 2;
                float b0 = bp2[col], b1v = bp2[col + 1];
                float v0 = silu(acc_b[mt][nt][0] + b0);
                float v1 = silu(acc_b[mt][nt][1] + b1v);
                float v2 = silu(acc_b[mt][nt][2] + b0);
                float v3 = silu(acc_b[mt][nt][3] + b1v);
                red_v2(g_aggr + (size_t)d0 * H + col, v0, v1);
                red_v2(g_aggr + (size_t)d1 * H + col, v2, v3);
            }
        }
        __syncthreads();   // sync 3: protect Hs/EsC/idx before next tile
        buf ^= 1;
    }
}

__global__ __launch_bounds__(H) void update_kernel(const float* lng, const float* lnb, int layer) {
    int n = blockIdx.x, c = threadIdx.x;
    float cnt = g_cnt[n];
    if (cnt < 1.f) cnt = 1.f;
    int idx = n * H + c;
    float v = g_x[idx] + g_aggr[idx] / cnt;
    g_aggr[idx] = 0.f;
    float mean, var;
    ln_stats(v, mean, var);
    float y = (v - mean) * rsqrtf(var + 1e-5f) * lng[layer * H + c] + lnb[layer * H + c];
    g_x[idx] = y;
    g_x_bf[idx] = __float2bfloat16(y);
}

__global__ __launch_bounds__(H) void pool_kernel(const int* bm) {
    int n = blockIdx.x, c = threadIdx.x;
    int g = bm[n];
    atomicAdd(&g_crystal[g * H + c], g_x[n * H + c]);
    if (c == 0) atomicAdd(&g_gcnt[g], 1.f);
}

__global__ __launch_bounds__(H) void head_kernel(const float* w1, const float* b1,
                                                 const float* w2, const float* b2,
                                                 const float* w3, const float* b3, float* out) {
    __shared__ float cr[H], h1s[H], h2s[64];
    int g = blockIdx.x, c = threadIdx.x;
    float gc = g_gcnt[g];
    if (gc < 1.f) gc = 1.f;
    cr[c] = g_crystal[g * H + c] / gc;
    __syncthreads();
    float a = b1[c];
    #pragma unroll 8
    for (int k = 0; k < H; k++) a += cr[k] * w1[k * H + c];
    h1s[c] = silu(a);
    __syncthreads();
    if (c < 64) {
        float a2 = b2[c];
        #pragma unroll 8
        for (int k = 0; k < H; k++) a2 += h1s[k] * w2[k * 64 + c];
        h2s[c] = silu(a2);
    }
    __syncthreads();
    if (c < 3) {
        float a3 = b3[c];
        #pragma unroll
        for (int k = 0; k < 64; k++) a3 += h2s[k] * w3[k * 3 + c];
        out[g * 3 + c] = a3;
    }
}

// ---------------- launch ----------------
extern "C" void kernel_launch(void* const* d_in, const int* in_sizes, int n_in,
                              void* d_out, int out_size) {
    const float* atom_fea   = (const float*)d_in[0];
    const float* nbr_fea    = (const float*)d_in[1];
    const int*   nbr_idx    = (const int*)d_in[2];
    const int*   batch_map  = (const int*)d_in[3];
    const float* emb_w      = (const float*)d_in[4];
    const float* emb_b      = (const float*)d_in[5];
    const float* emb_ln_g   = (const float*)d_in[6];
    const float* emb_ln_b   = (const float*)d_in[7];
    const float* edge_w     = (const float*)d_in[8];
    const float* edge_b     = (const float*)d_in[9];
    const float* conv_w1    = (const float*)d_in[10];
    const float* conv_b1    = (const float*)d_in[11];
    const float* conv_w2    = (const float*)d_in[12];
    const float* conv_b2    = (const float*)d_in[13];
    const float* ln_g       = (const float*)d_in[14];
    const float* ln_b       = (const float*)d_in[15];
    const float* out_w1     = (const float*)d_in[16];
    const float* out_b1     = (const float*)d_in[17];
    const float* out_w2     = (const float*)d_in[18];
    const float* out_b2     = (const float*)d_in[19];
    const float* out_w3     = (const float*)d_in[20];
    const float* out_b3     = (const float*)d_in[21];
    float* out = (float*)d_out;

    cudaFuncSetAttribute(conv_p_kernel, cudaFuncAttributeMaxDynamicSharedMemorySize, P_SMEM);
    cudaFuncSetAttribute(conv_edge,     cudaFuncAttributeMaxDynamicSharedMemorySize, CV_SMEM);

    zero_kernel<<<(N_NODES * H + 255) / 256, 256>>>();
    prep_w<<<(L * H2 * H2 + 255) / 256, 256>>>(conv_w1, conv_w2);
    node_embed<<<N_NODES, H>>>(atom_fea, emb_w, emb_b, emb_ln_g, emb_ln_b);
    edge_embed<<<N_EDGES / 128, 64>>>(nbr_fea, edge_w, edge_b);
    cnt_kernel<<<(N_EDGES + 255) / 256, 256>>>(nbr_idx);

    for (int l = 0; l < L; l++) {
        conv_p_kernel<<<dim3((N_NODES + 127) / 128, 2), 256, P_SMEM>>>(conv_b1, l);
        conv_edge<<<CV_GRID, 512, CV_SMEM>>>(nbr_idx, conv_b2, l);
        update_kernel<<<N_NODES, H>>>(ln_g, ln_b, l);
    }

    pool_kernel<<<N_NODES, H>>>(batch_map);
    head_kernel<<<N_GRAPHS, H>>>(out_w1, out_b1, out_w2, out_b2, out_w3, out_b3, out);
}

// round 12
// speedup vs baseline: 1.0923x; 1.0923x over previous
#include <cuda_runtime.h>
#include <cuda_bf16.h>
#include <cstdint>

#define N_NODES 50000
#define N_EDGES 800000
#define N_GRAPHS 1024
#define H 128
#define H2 256
#define L 5

// ---------------- scratch (__device__ globals: allowed) ----------------
__device__ float          g_x[N_NODES * H];
__device__ __nv_bfloat16  g_x_bf[N_NODES * H];
__device__ __nv_bfloat16  g_e_bf[(size_t)N_EDGES * H];
__device__ float          g_p[(size_t)N_NODES * H2];   // P = x @ W1_top + b1
__device__ float          g_aggr[N_NODES * H];
__device__ float          g_cnt[N_NODES];
__device__ float          g_crystal[N_GRAPHS * H];
__device__ float          g_gcnt[N_GRAPHS];
__device__ __nv_bfloat16  g_w1[L * H2 * H2];
__device__ __nv_bfloat16  g_w2[L * H2 * H];

__device__ __forceinline__ float silu(float x) { return x / (1.f + expf(-x)); }

// ---------------- PTX helpers ----------------
__device__ __forceinline__ void ldsm_x4(uint32_t r[4], const void* p) {
    uint32_t a = (uint32_t)__cvta_generic_to_shared(p);
    asm volatile("ldmatrix.sync.aligned.m8n8.x4.shared.b16 {%0,%1,%2,%3},[%4];\n"
                 : "=r"(r[0]), "=r"(r[1]), "=r"(r[2]), "=r"(r[3]) : "r"(a));
}
__device__ __forceinline__ void ldsm_x4t(uint32_t r[4], const void* p) {
    uint32_t a = (uint32_t)__cvta_generic_to_shared(p);
    asm volatile("ldmatrix.sync.aligned.m8n8.x4.trans.shared.b16 {%0,%1,%2,%3},[%4];\n"
                 : "=r"(r[0]), "=r"(r[1]), "=r"(r[2]), "=r"(r[3]) : "r"(a));
}
__device__ __forceinline__ void mma_bf16(float d[4], const uint32_t a[4], uint32_t b0, uint32_t b1) {
    asm volatile(
        "mma.sync.aligned.m16n8k16.row.col.f32.bf16.bf16.f32 "
        "{%0,%1,%2,%3},{%4,%5,%6,%7},{%8,%9},{%0,%1,%2,%3};\n"
        : "+f"(d[0]), "+f"(d[1]), "+f"(d[2]), "+f"(d[3])
        : "r"(a[0]), "r"(a[1]), "r"(a[2]), "r"(a[3]), "r"(b0), "r"(b1));
}
__device__ __forceinline__ void red_v4(float* p, float a, float b, float c, float d) {
    asm volatile("red.global.add.v4.f32 [%0], {%1,%2,%3,%4};\n"
                 :: "l"(p), "f"(a), "f"(b), "f"(c), "f"(d) : "memory");
}
__device__ __forceinline__ void cp16(void* s, const void* g) {
    uint32_t sa = (uint32_t)__cvta_generic_to_shared(s);
    asm volatile("cp.async.cg.shared.global [%0],[%1],16;\n" :: "r"(sa), "l"(g));
}
#define CP_COMMIT() asm volatile("cp.async.commit_group;\n")
#define CP_WAIT(n)  asm volatile("cp.async.wait_group %0;\n" :: "n"(n))

// ---------------- small kernels ----------------
// g_aggr is left zero by update_kernel at the end of every layer (and starts
// zero-initialized), so only cnt/crystal/gcnt need clearing per launch.
__global__ void zero_kernel() {
    int i = blockIdx.x * 256 + threadIdx.x;
    if (i < N_NODES)      g_cnt[i] = 0.f;
    if (i < N_GRAPHS * H) g_crystal[i] = 0.f;
    if (i < N_GRAPHS)     g_gcnt[i] = 0.f;
}

__global__ void prep_w(const float* w1, const float* w2) {
    int i = blockIdx.x * 256 + threadIdx.x;
    if (i < L * H2 * H2) g_w1[i] = __float2bfloat16(w1[i]);
    if (i < L * H2 * H)  g_w2[i] = __float2bfloat16(w2[i]);
}

__device__ __forceinline__ void ln_stats(float v, float& mean, float& var) {
    __shared__ float red[8];
    int lane = threadIdx.x & 31, wid = threadIdx.x >> 5;
    float s = v;
    #pragma unroll
    for (int o = 16; o; o >>= 1) s += __shfl_xor_sync(0xffffffffu, s, o);
    if (!lane) red[wid] = s;
    __syncthreads();
    mean = (red[0] + red[1] + red[2] + red[3]) * (1.f / H);
    float d = v - mean, sq = d * d;
    #pragma unroll
    for (int o = 16; o; o >>= 1) sq += __shfl_xor_sync(0xffffffffu, sq, o);
    if (!lane) red[4 + wid] = sq;
    __syncthreads();
    var = (red[4] + red[5] + red[6] + red[7]) * (1.f / H);
}

__global__ __launch_bounds__(H) void node_embed(const float* atom, const float* w,
                                                const float* b, const float* lg, const float* lb) {
    int n = blockIdx.x, c = threadIdx.x;
    float a0 = atom[n * 4 + 0], a1 = atom[n * 4 + 1], a2 = atom[n * 4 + 2], a3 = atom[n * 4 + 3];
    float v = b[c] + a0 * w[c] + a1 * w[H + c] + a2 * w[2 * H + c] + a3 * w[3 * H + c];
    float mean, var;
    ln_stats(v, mean, var);
    float y = (v - mean) * rsqrtf(var + 1e-5f) * lg[c] + lb[c];
    y = silu(y);
    g_x[n * H + c] = y;
    g_x_bf[n * H + c] = __float2bfloat16(y);
}

__global__ __launch_bounds__(64) void edge_embed(const float* nf, const float* w, const float* b) {
    __shared__ float nfs[128 * 42];
    int t = threadIdx.x;
    int e0 = blockIdx.x * 128;
    float wr0[41], wr1[41];
    #pragma unroll
    for (int k = 0; k < 41; k++) { wr0[k] = w[k * H + 2 * t]; wr1[k] = w[k * H + 2 * t + 1]; }
    float b0 = b[2 * t], b1 = b[2 * t + 1];
    for (int i = t; i < 128 * 41; i += 64)
        nfs[(i / 41) * 42 + (i % 41)] = nf[(size_t)e0 * 41 + i];
    __syncthreads();
    #pragma unroll 2
    for (int e = 0; e < 128; e++) {
        float a0 = b0, a1 = b1;
        #pragma unroll
        for (int k = 0; k < 41; k++) {
            float v = nfs[e * 42 + k];
            a0 += v * wr0[k];
            a1 += v * wr1[k];
        }
        __nv_bfloat162 o;
        o.x = __float2bfloat16(silu(a0));
        o.y = __float2bfloat16(silu(a1));
        *(__nv_bfloat162*)(g_e_bf + (size_t)(e0 + e) * H + 2 * t) = o;
    }
}

__global__ void cnt_kernel(const int* nbr) {
    int i = blockIdx.x * 256 + threadIdx.x;
    if (i < N_EDGES) atomicAdd(&g_cnt[nbr[2 * i + 1]], 1.f);
}

extern __shared__ char smem_raw[];

// ================= node GEMM: P = x_bf @ W1_top + b1 (fp32 out) =============
#define PAS_LD 136
#define PBS_LD 136
#define P_SMEM (128 * PAS_LD * 2 + 2 * 64 * PBS_LD * 2)

__global__ __launch_bounds__(256, 2) void conv_p_kernel(const float* cb1, int layer) {
    __nv_bfloat16* As = (__nv_bfloat16*)smem_raw;
    __nv_bfloat16* Bs = As + 128 * PAS_LD;
    const int tid = threadIdx.x;
    const int n0 = blockIdx.x * 128, nh = blockIdx.y;
    const __nv_bfloat16* W = g_w1 + (size_t)layer * H2 * H2;   // rows 0..127 = W1_top
    const int lane = tid & 31, warp = tid >> 5;
    const int wm = warp & 3, wn = warp >> 2;   // 4 x 2 warps: M32 x N64

    #pragma unroll
    for (int i = 0; i < 8; i++) {
        int idx = i * 256 + tid;
        int row = idx >> 4, col = (idx & 15) << 3;
        int nr = n0 + row; if (nr >= N_NODES) nr = 0;
        cp16(As + row * PAS_LD + col, g_x_bf + (size_t)nr * H + col);
    }
    CP_COMMIT();
    #pragma unroll
    for (int kt = 0; kt < 2; kt++) {
        #pragma unroll
        for (int i = 0; i < 4; i++) {
            int idx = i * 256 + tid;
            int row = idx >> 4, col = (idx & 15) << 3;
            cp16(Bs + kt * 64 * PBS_LD + row * PBS_LD + col,
                 W + (size_t)(kt * 64 + row) * H2 + nh * 128 + col);
        }
        CP_COMMIT();
    }

    float acc[2][8][4];
    #pragma unroll
    for (int mt = 0; mt < 2; mt++)
        #pragma unroll
        for (int nt = 0; nt < 8; nt++)
            #pragma unroll
            for (int j = 0; j < 4; j++) acc[mt][nt][j] = 0.f;

    #pragma unroll
    for (int kt = 0; kt < 2; kt++) {
        if (kt == 0) CP_WAIT(1); else CP_WAIT(0);
        __syncthreads();
        const __nv_bfloat16* Bt = Bs + kt * 64 * PBS_LD;
        #pragma unroll
        for (int k16 = 0; k16 < 4; k16++) {
            uint32_t af[2][4];
            #pragma unroll
            for (int mt = 0; mt < 2; mt++)
                ldsm_x4(af[mt], As + (wm * 32 + mt * 16 + (lane & 15)) * PAS_LD
                                  + kt * 64 + k16 * 16 + ((lane >> 4) << 3));
            uint32_t bfr[4][4];
            #pragma unroll
            for (int q = 0; q < 4; q++)
                ldsm_x4t(bfr[q], Bt + (k16 * 16 + (lane & 15)) * PBS_LD
                                   + wn * 64 + q * 16 + ((lane >> 4) << 3));
            #pragma unroll
            for (int mt = 0; mt < 2; mt++)
                #pragma unroll
                for (int nt = 0; nt < 8; nt++)
                    mma_bf16(acc[mt][nt], af[mt], bfr[nt >> 1][(nt & 1) * 2], bfr[nt >> 1][(nt & 1) * 2 + 1]);
        }
    }

    const float* bp = cb1 + layer * H2 + nh * 128;
    #pragma unroll
    for (int mt = 0; mt < 2; mt++) {
        int r = wm * 32 + mt * 16 + (lane >> 2);
        #pragma unroll
        for (int nt = 0; nt < 8; nt++) {
            int col = wn * 64 + nt * 8 + (lane & 3) * 2;
            float b0 = bp[col], b1v = bp[col + 1];
            if (n0 + r < N_NODES) {
                float2 v = {acc[mt][nt][0] + b0, acc[mt][nt][1] + b1v};
                *(float2*)(g_p + (size_t)(n0 + r) * H2 + nh * 128 + col) = v;
            }
            if (n0 + r + 8 < N_NODES) {
                float2 v = {acc[mt][nt][2] + b0, acc[mt][nt][3] + b1v};
                *(float2*)(g_p + (size_t)(n0 + r + 8) * H2 + nh * 128 + col) = v;
            }
        }
    }
}

// ================= fused edge conv, M=128, 2 CTAs/SM =================
// Phase A (stages 0..3): Q = e @ W1_bot; h1 = silu(Q + P[src]).
//   h1 cols 0..127   -> Hs0 panel
//   h1 cols 128..255 -> Es panel (e is dead after stage 3's MMA; sync first)
// Phase B (stages 4..7): aggr[dst] += silu(h1 @ W2 + b2), h1 read from Hs0|Es.
#define E_LD  136
#define EB_LD 136
#define SM_ES   0
#define SM_HS0  (128 * E_LD * 2)
#define SM_EBS  (SM_HS0 + 128 * E_LD * 2)
#define SM_EIDX (SM_EBS + 2 * 64 * EB_LD * 2)
#define E_SMEM  (SM_EIDX + 2 * 128 * 4)

__global__ __launch_bounds__(256, 2) void conv_edge(const int* nbr, const float* cb2, int layer) {
    __nv_bfloat16* Es  = (__nv_bfloat16*)(smem_raw + SM_ES);
    __nv_bfloat16* Hs0 = (__nv_bfloat16*)(smem_raw + SM_HS0);
    __nv_bfloat16* Bsm = (__nv_bfloat16*)(smem_raw + SM_EBS);
    int* srcs = (int*)(smem_raw + SM_EIDX);
    int* dsts = srcs + 128;

    const int tid = threadIdx.x, tile = blockIdx.x;
    const int lane = tid & 31, warp = tid >> 5;
    const int wm = warp & 3, wn = warp >> 2;   // 4 x 2 warps: M32 x N64
    const __nv_bfloat16* W1 = g_w1 + (size_t)layer * H2 * H2;  // W1_bot = rows 128..255
    const __nv_bfloat16* W2 = g_w2 + (size_t)layer * H2 * H;

    if (tid < 128) {
        int2 pr = ((const int2*)nbr)[tile * 128 + tid];
        srcs[tid] = pr.x;
        dsts[tid] = pr.y;
    }

    // E panel: e[tile*128 .. +127][0..127]
    #pragma unroll
    for (int i = 0; i < 8; i++) {
        int idx = i * 256 + tid;
        int row = idx >> 4, col = (idx & 15) << 3;
        cp16(Es + row * E_LD + col, g_e_bf + (size_t)(tile * 128 + row) * H + col);
    }
    CP_COMMIT();

    auto ldB = [&](int t) {
        const __nv_bfloat16* wt;
        int rs;
        if (t < 4) { int half = t >> 1, kt = t & 1;
                     wt = W1 + (size_t)(128 + kt * 64) * H2 + half * 128; rs = H2; }
        else       { int kt = t - 4; wt = W2 + (size_t)(kt * 64) * H;     rs = H;  }
        __nv_bfloat16* dst = Bsm + (t & 1) * (64 * EB_LD);
        #pragma unroll
        for (int i = 0; i < 4; i++) {
            int idx = i * 256 + tid;
            int row = idx >> 4, col = (idx & 15) << 3;
            cp16(dst + row * EB_LD + col, wt + (size_t)row * rs + col);
        }
    };

    ldB(0);
    CP_COMMIT();

    // -------- Phase A --------
    {
        float acc_a[2][8][4];
        #pragma unroll
        for (int mt = 0; mt < 2; mt++)
            #pragma unroll
            for (int nt = 0; nt < 8; nt++)
                #pragma unroll
                for (int j = 0; j < 4; j++) acc_a[mt][nt][j] = 0.f;

        #pragma unroll
        for (int t = 0; t < 4; t++) {
            ldB(t + 1); CP_COMMIT(); CP_WAIT(1);
            __syncthreads();

            const int kbase = (t & 1) * 64;
            const __nv_bfloat16* Bt = Bsm + (t & 1) * (64 * EB_LD);
            #pragma unroll
            for (int k16 = 0; k16 < 4; k16++) {
                uint32_t af[2][4];
                #pragma unroll
                for (int mt = 0; mt < 2; mt++)
                    ldsm_x4(af[mt], Es + (wm * 32 + mt * 16 + (lane & 15)) * E_LD
                                      + kbase + k16 * 16 + ((lane >> 4) << 3));
                uint32_t bfr[4][4];
                #pragma unroll
                for (int q = 0; q < 4; q++)
                    ldsm_x4t(bfr[q], Bt + (k16 * 16 + (lane & 15)) * EB_LD
                                       + wn * 64 + q * 16 + ((lane >> 4) << 3));
                #pragma unroll
                for (int mt = 0; mt < 2; mt++)
                    #pragma unroll
                    for (int nt = 0; nt < 8; nt++)
                        mma_bf16(acc_a[mt][nt], af[mt], bfr[nt >> 1][(nt & 1) * 2], bfr[nt >> 1][(nt & 1) * 2 + 1]);
            }

            if (t & 1) {
                const int half = t >> 1;
                if (half == 1) __syncthreads();   // all warps done reading Es before overwrite
                __nv_bfloat16* Ht = half ? Es : Hs0;
                #pragma unroll
                for (int mt = 0; mt < 2; mt++) {
                    int rloc = wm * 32 + mt * 16 + (lane >> 2);
                    int s0 = srcs[rloc], s1 = srcs[rloc + 8];
                    #pragma unroll
                    for (int nt = 0; nt < 8; nt++) {
                        int lcol = wn * 64 + nt * 8 + (lane & 3) * 2;
                        int gcol = half * 128 + lcol;
                        float2 p0 = *(const float2*)(g_p + (size_t)s0 * H2 + gcol);
                        float2 p1 = *(const float2*)(g_p + (size_t)s1 * H2 + gcol);
                        __nv_bfloat162 v01, v23;
                        v01.x = __float2bfloat16(silu(acc_a[mt][nt][0] + p0.x));
                        v01.y = __float2bfloat16(silu(acc_a[mt][nt][1] + p0.y));
                        v23.x = __float2bfloat16(silu(acc_a[mt][nt][2] + p1.x));
                        v23.y = __float2bfloat16(silu(acc_a[mt][nt][3] + p1.y));
                        *(__nv_bfloat162*)(Ht + (size_t)rloc * E_LD + lcol) = v01;
                        *(__nv_bfloat162*)(Ht + (size_t)(rloc + 8) * E_LD + lcol) = v23;
                        acc_a[mt][nt][0] = acc_a[mt][nt][1] = acc_a[mt][nt][2] = acc_a[mt][nt][3] = 0.f;
                    }
                }
            }
            __syncthreads();
        }
    }

    // -------- Phase B --------
    float acc_b[2][8][4];
    #pragma unroll
    for (int mt = 0; mt < 2; mt++)
        #pragma unroll
        for (int nt = 0; nt < 8; nt++)
            #pragma unroll
            for (int j = 0; j < 4; j++) acc_b[mt][nt][j] = 0.f;

    #pragma unroll
    for (int t = 4; t < 8; t++) {
        if (t < 7) { ldB(t + 1); CP_COMMIT(); CP_WAIT(1); }
        else       { CP_WAIT(0); }
        __syncthreads();

        const int kb = t - 4;                       // compile-time after unroll
        const __nv_bfloat16* Apan = (kb < 2) ? Hs0 : Es;
        const int kbase = (kb & 1) * 64;
        const __nv_bfloat16* Bt = Bsm + (t & 1) * (64 * EB_LD);
        #pragma unroll
        for (int k16 = 0; k16 < 4; k16++) {
            uint32_t af[2][4];
            #pragma unroll
            for (int mt = 0; mt < 2; mt++)
                ldsm_x4(af[mt], Apan + (wm * 32 + mt * 16 + (lane & 15)) * E_LD
                                  + kbase + k16 * 16 + ((lane >> 4) << 3));
            uint32_t bfr[4][4];
            #pragma unroll
            for (int q = 0; q < 4; q++)
                ldsm_x4t(bfr[q], Bt + (k16 * 16 + (lane & 15)) * EB_LD
                                   + wn * 64 + q * 16 + ((lane >> 4) << 3));
            #pragma unroll
            for (int mt = 0; mt < 2; mt++)
                #pragma unroll
                for (int nt = 0; nt < 8; nt++)
                    mma_bf16(acc_b[mt][nt], af[mt], bfr[nt >> 1][(nt & 1) * 2], bfr[nt >> 1][(nt & 1) * 2 + 1]);
        }
        __syncthreads();
    }

    // phase B epilogue: silu + bias, then lane-pair butterfly -> one red.v4
    // per thread (even lane-quad: row rloc cols c..c+3; odd: row rloc+8).
    const float* bp = cb2 + layer * H;
    const int q = lane & 3;
    const bool evenq = (q & 1) == 0;
    #pragma unroll
    for (int mt = 0; mt < 2; mt++) {
        int rloc = wm * 32 + mt * 16 + (lane >> 2);
        int d0 = dsts[rloc], d1 = dsts[rloc + 8];
        #pragma unroll
        for (int nt = 0; nt < 8; nt++) {
            int col = wn * 64 + nt * 8 + q * 2;
            float b0 = bp[col], b1v = bp[col + 1];
            float v0 = silu(acc_b[mt][nt][0] + b0);    // row rloc,   col
            float v1 = silu(acc_b[mt][nt][1] + b1v);   // row rloc,   col+1
            float v2 = silu(acc_b[mt][nt][2] + b0);    // row rloc+8, col
            float v3 = silu(acc_b[mt][nt][3] + b1v);   // row rloc+8, col+1
            float sa = evenq ? v2 : v0;
            float sb = evenq ? v3 : v1;
            float ra = __shfl_xor_sync(0xffffffffu, sa, 1);
            float rb = __shfl_xor_sync(0xffffffffu, sb, 1);
            if (evenq) {
                // receives partner's (v0,v1) = row rloc cols col+2..col+3
                red_v4(g_aggr + (size_t)d0 * H + col, v0, v1, ra, rb);
            } else {
                // receives partner's (v2,v3) = row rloc+8 cols col-2..col-1
                red_v4(g_aggr + (size_t)d1 * H + col - 2, ra, rb, v2, v3);
            }
        }
    }
}

__global__ __launch_bounds__(H) void update_kernel(const float* lng, const float* lnb, int layer) {
    int n = blockIdx.x, c = threadIdx.x;
    float cnt = g_cnt[n];
    if (cnt < 1.f) cnt = 1.f;
    int idx = n * H + c;
    float v = g_x[idx] + g_aggr[idx] / cnt;
    g_aggr[idx] = 0.f;
    float mean, var;
    ln_stats(v, mean, var);
    float y = (v - mean) * rsqrtf(var + 1e-5f) * lng[layer * H + c] + lnb[layer * H + c];
    g_x[idx] = y;
    g_x_bf[idx] = __float2bfloat16(y);
}

__global__ __launch_bounds__(H) void pool_kernel(const int* bm) {
    int n = blockIdx.x, c = threadIdx.x;
    int g = bm[n];
    atomicAdd(&g_crystal[g * H + c], g_x[n * H + c]);
    if (c == 0) atomicAdd(&g_gcnt[g], 1.f);
}

__global__ __launch_bounds__(H) void head_kernel(const float* w1, const float* b1,
                                                 const float* w2, const float* b2,
                                                 const float* w3, const float* b3, float* out) {
    __shared__ float cr[H], h1s[H], h2s[64];
    int g = blockIdx.x, c = threadIdx.x;
    float gc = g_gcnt[g];
    if (gc < 1.f) gc = 1.f;
    cr[c] = g_crystal[g * H + c] / gc;
    __syncthreads();
    float a = b1[c];
    #pragma unroll 8
    for (int k = 0; k < H; k++) a += cr[k] * w1[k * H + c];
    h1s[c] = silu(a);
    __syncthreads();
    if (c < 64) {
        float a2 = b2[c];
        #pragma unroll 8
        for (int k = 0; k < H; k++) a2 += h1s[k] * w2[k * 64 + c];
        h2s[c] = silu(a2);
    }
    __syncthreads();
    if (c < 3) {
        float a3 = b3[c];
        #pragma unroll
        for (int k = 0; k < 64; k++) a3 += h2s[k] * w3[k * 3 + c];
        out[g * 3 + c] = a3;
    }
}

// ---------------- launch ----------------
extern "C" void kernel_launch(void* const* d_in, const int* in_sizes, int n_in,
                              void* d_out, int out_size) {
    const float* atom_fea   = (const float*)d_in[0];
    const float* nbr_fea    = (const float*)d_in[1];
    const int*   nbr_idx    = (const int*)d_in[2];
    const int*   batch_map  = (const int*)d_in[3];
    const float* emb_w      = (const float*)d_in[4];
    const float* emb_b      = (const float*)d_in[5];
    const float* emb_ln_g   = (const float*)d_in[6];
    const float* emb_ln_b   = (const float*)d_in[7];
    const float* edge_w     = (const float*)d_in[8];
    const float* edge_b     = (const float*)d_in[9];
    const float* conv_w1    = (const float*)d_in[10];
    const float* conv_b1    = (const float*)d_in[11];
    const float* conv_w2    = (const float*)d_in[12];
    const float* conv_b2    = (const float*)d_in[13];
    const float* ln_g       = (const float*)d_in[14];
    const float* ln_b       = (const float*)d_in[15];
    const float* out_w1     = (const float*)d_in[16];
    const float* out_b1     = (const float*)d_in[17];
    const float* out_w2     = (const float*)d_in[18];
    const float* out_b2     = (const float*)d_in[19];
    const float* out_w3     = (const float*)d_in[20];
    const float* out_b3     = (const float*)d_in[21];
    float* out = (float*)d_out;

    cudaFuncSetAttribute(conv_p_kernel, cudaFuncAttributeMaxDynamicSharedMemorySize, P_SMEM);
    cudaFuncSetAttribute(conv_edge,     cudaFuncAttributeMaxDynamicSharedMemorySize, E_SMEM);

    zero_kernel<<<(N_GRAPHS * H + 255) / 256, 256>>>();
    prep_w<<<(L * H2 * H2 + 255) / 256, 256>>>(conv_w1, conv_w2);
    node_embed<<<N_NODES, H>>>(atom_fea, emb_w, emb_b, emb_ln_g, emb_ln_b);
    edge_embed<<<N_EDGES / 128, 64>>>(nbr_fea, edge_w, edge_b);
    cnt_kernel<<<(N_EDGES + 255) / 256, 256>>>(nbr_idx);

    for (int l = 0; l < L; l++) {
        conv_p_kernel<<<dim3((N_NODES + 127) / 128, 2), 256, P_SMEM>>>(conv_b1, l);
        conv_edge<<<N_EDGES / 128, 256, E_SMEM>>>(nbr_idx, conv_b2, l);
        update_kernel<<<N_NODES, H>>>(ln_g, ln_b, l);
    }

    pool_kernel<<<N_NODES, H>>>(batch_map);
    head_kernel<<<N_GRAPHS, H>>>(out_w1, out_b1, out_w2, out_b2, out_w3, out_b3, out);
}

// round 14
// speedup vs baseline: 1.1086x; 1.0149x over previous
#include <cuda_runtime.h>
#include <cuda_bf16.h>
#include <cstdint>

#define N_NODES 50000
#define N_EDGES 800000
#define N_GRAPHS 1024
#define H 128
#define H2 256
#define L 5

// ---------------- scratch (__device__ globals: allowed) ----------------
__device__ float          g_x[N_NODES * H];
__device__ __nv_bfloat16  g_x_bf[N_NODES * H];
__device__ __nv_bfloat16  g_e_bf[(size_t)N_EDGES * H];
__device__ float          g_p[(size_t)N_NODES * H2];   // P = x @ W1_top + b1
__device__ float          g_aggr[N_NODES * H];
__device__ float          g_cnt[N_NODES];
__device__ float          g_crystal[N_GRAPHS * H];
__device__ float          g_gcnt[N_GRAPHS];
__device__ __nv_bfloat16  g_w1[L * H2 * H2];
__device__ __nv_bfloat16  g_w2[L * H2 * H];

__device__ __forceinline__ float silu(float x) { return x / (1.f + expf(-x)); }

// ---------------- PTX helpers ----------------
__device__ __forceinline__ void ldsm_x4(uint32_t r[4], const void* p) {
    uint32_t a = (uint32_t)__cvta_generic_to_shared(p);
    asm volatile("ldmatrix.sync.aligned.m8n8.x4.shared.b16 {%0,%1,%2,%3},[%4];\n"
                 : "=r"(r[0]), "=r"(r[1]), "=r"(r[2]), "=r"(r[3]) : "r"(a));
}
__device__ __forceinline__ void ldsm_x4t(uint32_t r[4], const void* p) {
    uint32_t a = (uint32_t)__cvta_generic_to_shared(p);
    asm volatile("ldmatrix.sync.aligned.m8n8.x4.trans.shared.b16 {%0,%1,%2,%3},[%4];\n"
                 : "=r"(r[0]), "=r"(r[1]), "=r"(r[2]), "=r"(r[3]) : "r"(a));
}
__device__ __forceinline__ void mma_bf16(float d[4], const uint32_t a[4], uint32_t b0, uint32_t b1) {
    asm volatile(
        "mma.sync.aligned.m16n8k16.row.col.f32.bf16.bf16.f32 "
        "{%0,%1,%2,%3},{%4,%5,%6,%7},{%8,%9},{%0,%1,%2,%3};\n"
        : "+f"(d[0]), "+f"(d[1]), "+f"(d[2]), "+f"(d[3])
        : "r"(a[0]), "r"(a[1]), "r"(a[2]), "r"(a[3]), "r"(b0), "r"(b1));
}
__device__ __forceinline__ void red_v2(float* p, float a, float b) {
    asm volatile("red.global.add.v2.f32 [%0], {%1,%2};\n" :: "l"(p), "f"(a), "f"(b) : "memory");
}
__device__ __forceinline__ void cp16(void* s, const void* g) {
    uint32_t sa = (uint32_t)__cvta_generic_to_shared(s);
    asm volatile("cp.async.cg.shared.global [%0],[%1],16;\n" :: "r"(sa), "l"(g));
}
#define CP_COMMIT() asm volatile("cp.async.commit_group;\n")
#define CP_WAIT(n)  asm volatile("cp.async.wait_group %0;\n" :: "n"(n))

// ---------------- small kernels ----------------
// g_aggr starts zero (static init) and is re-zeroed by update_kernel each
// layer, so only cnt/crystal/gcnt need clearing per launch.
__global__ void zero_kernel() {
    int i = blockIdx.x * 256 + threadIdx.x;
    if (i < N_NODES)      g_cnt[i] = 0.f;
    if (i < N_GRAPHS * H) g_crystal[i] = 0.f;
    if (i < N_GRAPHS)     g_gcnt[i] = 0.f;
}

__global__ void prep_w(const float* w1, const float* w2) {
    int i = blockIdx.x * 256 + threadIdx.x;
    if (i < L * H2 * H2) g_w1[i] = __float2bfloat16(w1[i]);
    if (i < L * H2 * H)  g_w2[i] = __float2bfloat16(w2[i]);
}

__device__ __forceinline__ void ln_stats(float v, float& mean, float& var) {
    __shared__ float red[8];
    int lane = threadIdx.x & 31, wid = threadIdx.x >> 5;
    float s = v;
    #pragma unroll
    for (int o = 16; o; o >>= 1) s += __shfl_xor_sync(0xffffffffu, s, o);
    if (!lane) red[wid] = s;
    __syncthreads();
    mean = (red[0] + red[1] + red[2] + red[3]) * (1.f / H);
    float d = v - mean, sq = d * d;
    #pragma unroll
    for (int o = 16; o; o >>= 1) sq += __shfl_xor_sync(0xffffffffu, sq, o);
    if (!lane) red[4 + wid] = sq;
    __syncthreads();
    var = (red[4] + red[5] + red[6] + red[7]) * (1.f / H);
}

__global__ __launch_bounds__(H) void node_embed(const float* atom, const float* w,
                                                const float* b, const float* lg, const float* lb) {
    int n = blockIdx.x, c = threadIdx.x;
    float a0 = atom[n * 4 + 0], a1 = atom[n * 4 + 1], a2 = atom[n * 4 + 2], a3 = atom[n * 4 + 3];
    float v = b[c] + a0 * w[c] + a1 * w[H + c] + a2 * w[2 * H + c] + a3 * w[3 * H + c];
    float mean, var;
    ln_stats(v, mean, var);
    float y = (v - mean) * rsqrtf(var + 1e-5f) * lg[c] + lb[c];
    y = silu(y);
    g_x[n * H + c] = y;
    g_x_bf[n * H + c] = __float2bfloat16(y);
}

// 64 edges/block (11.3 KB smem -> ~3x occupancy), float4 smem reads.
// nfs rows padded to 44 floats (16B-aligned); weights zero-padded to 44.
__global__ __launch_bounds__(64) void edge_embed(const float* nf, const float* w, const float* b) {
    __shared__ float nfs[64 * 44];
    int t = threadIdx.x;
    int e0 = blockIdx.x * 64;
    float wr0[44], wr1[44];
    #pragma unroll
    for (int k = 0; k < 41; k++) { wr0[k] = w[k * H + 2 * t]; wr1[k] = w[k * H + 2 * t + 1]; }
    #pragma unroll
    for (int k = 41; k < 44; k++) { wr0[k] = 0.f; wr1[k] = 0.f; }
    float b0 = b[2 * t], b1 = b[2 * t + 1];
    for (int i = t; i < 64 * 41; i += 64)
        nfs[(i / 41) * 44 + (i % 41)] = nf[(size_t)e0 * 41 + i];
    // zero pad (t indexes the row; 64 threads cover all 64 rows)
    nfs[t * 44 + 41] = 0.f;
    nfs[t * 44 + 42] = 0.f;
    nfs[t * 44 + 43] = 0.f;
    __syncthreads();
    #pragma unroll 2
    for (int e = 0; e < 64; e++) {
        float a0 = b0, a1 = b1;
        #pragma unroll
        for (int k4 = 0; k4 < 11; k4++) {
            float4 v = *(const float4*)&nfs[e * 44 + k4 * 4];
            a0 += v.x * wr0[k4 * 4 + 0]; a1 += v.x * wr1[k4 * 4 + 0];
            a0 += v.y * wr0[k4 * 4 + 1]; a1 += v.y * wr1[k4 * 4 + 1];
            a0 += v.z * wr0[k4 * 4 + 2]; a1 += v.z * wr1[k4 * 4 + 2];
            a0 += v.w * wr0[k4 * 4 + 3]; a1 += v.w * wr1[k4 * 4 + 3];
        }
        __nv_bfloat162 o;
        o.x = __float2bfloat16(silu(a0));
        o.y = __float2bfloat16(silu(a1));
        *(__nv_bfloat162*)(g_e_bf + (size_t)(e0 + e) * H + 2 * t) = o;
    }
}

__global__ void cnt_kernel(const int* nbr) {
    int i = blockIdx.x * 256 + threadIdx.x;
    if (i < N_EDGES) atomicAdd(&g_cnt[nbr[2 * i + 1]], 1.f);
}

extern __shared__ char smem_raw[];

// ================= node GEMM: P = x_bf @ W1_top + b1 (fp32 out) =============
#define PAS_LD 136
#define PBS_LD 136
#define P_SMEM (128 * PAS_LD * 2 + 2 * 64 * PBS_LD * 2)

__global__ __launch_bounds__(256, 2) void conv_p_kernel(const float* cb1, int layer) {
    __nv_bfloat16* As = (__nv_bfloat16*)smem_raw;
    __nv_bfloat16* Bs = As + 128 * PAS_LD;
    const int tid = threadIdx.x;
    const int n0 = blockIdx.x * 128, nh = blockIdx.y;
    const __nv_bfloat16* W = g_w1 + (size_t)layer * H2 * H2;   // rows 0..127 = W1_top
    const int lane = tid & 31, warp = tid >> 5;
    const int wm = warp & 3, wn = warp >> 2;   // 4 x 2 warps: M32 x N64

    #pragma unroll
    for (int i = 0; i < 8; i++) {
        int idx = i * 256 + tid;
        int row = idx >> 4, col = (idx & 15) << 3;
        int nr = n0 + row; if (nr >= N_NODES) nr = 0;
        cp16(As + row * PAS_LD + col, g_x_bf + (size_t)nr * H + col);
    }
    CP_COMMIT();
    #pragma unroll
    for (int kt = 0; kt < 2; kt++) {
        #pragma unroll
        for (int i = 0; i < 4; i++) {
            int idx = i * 256 + tid;
            int row = idx >> 4, col = (idx & 15) << 3;
            cp16(Bs + kt * 64 * PBS_LD + row * PBS_LD + col,
                 W + (size_t)(kt * 64 + row) * H2 + nh * 128 + col);
        }
        CP_COMMIT();
    }

    float acc[2][8][4];
    #pragma unroll
    for (int mt = 0; mt < 2; mt++)
        #pragma unroll
        for (int nt = 0; nt < 8; nt++)
            #pragma unroll
            for (int j = 0; j < 4; j++) acc[mt][nt][j] = 0.f;

    #pragma unroll
    for (int kt = 0; kt < 2; kt++) {
        if (kt == 0) CP_WAIT(1); else CP_WAIT(0);
        __syncthreads();
        const __nv_bfloat16* Bt = Bs + kt * 64 * PBS_LD;
        #pragma unroll
        for (int k16 = 0; k16 < 4; k16++) {
            uint32_t af[2][4];
            #pragma unroll
            for (int mt = 0; mt < 2; mt++)
                ldsm_x4(af[mt], As + (wm * 32 + mt * 16 + (lane & 15)) * PAS_LD
                                  + kt * 64 + k16 * 16 + ((lane >> 4) << 3));
            uint32_t bfr[4][4];
            #pragma unroll
            for (int q = 0; q < 4; q++)
                ldsm_x4t(bfr[q], Bt + (k16 * 16 + (lane & 15)) * PBS_LD
                                   + wn * 64 + q * 16 + ((lane >> 4) << 3));
            #pragma unroll
            for (int mt = 0; mt < 2; mt++)
                #pragma unroll
                for (int nt = 0; nt < 8; nt++)
                    mma_bf16(acc[mt][nt], af[mt], bfr[nt >> 1][(nt & 1) * 2], bfr[nt >> 1][(nt & 1) * 2 + 1]);
        }
    }

    const float* bp = cb1 + layer * H2 + nh * 128;
    #pragma unroll
    for (int mt = 0; mt < 2; mt++) {
        int r = wm * 32 + mt * 16 + (lane >> 2);
        #pragma unroll
        for (int nt = 0; nt < 8; nt++) {
            int col = wn * 64 + nt * 8 + (lane & 3) * 2;
            float b0 = bp[col], b1v = bp[col + 1];
            if (n0 + r < N_NODES) {
                float2 v = {acc[mt][nt][0] + b0, acc[mt][nt][1] + b1v};
                *(float2*)(g_p + (size_t)(n0 + r) * H2 + nh * 128 + col) = v;
            }
            if (n0 + r + 8 < N_NODES) {
                float2 v = {acc[mt][nt][2] + b0, acc[mt][nt][3] + b1v};
                *(float2*)(g_p + (size_t)(n0 + r + 8) * H2 + nh * 128 + col) = v;
            }
        }
    }
}

// ================= fused edge conv, M=128, 2 CTAs/SM (R7-proven) =============
// Phase A (stages 0..3): Q = e @ W1_bot; h1 = silu(Q + P[src]).
//   h1 cols 0..127   -> Hs0 panel
//   h1 cols 128..255 -> Es panel (e is dead after stage 3's MMA; sync first)
// Phase B (stages 4..7): aggr[dst] += silu(h1 @ W2 + b2), h1 read from Hs0|Es.
#define E_LD  136
#define EB_LD 136
#define SM_ES   0
#define SM_HS0  (128 * E_LD * 2)
#define SM_EBS  (SM_HS0 + 128 * E_LD * 2)
#define SM_EIDX (SM_EBS + 2 * 64 * EB_LD * 2)
#define E_SMEM  (SM_EIDX + 2 * 128 * 4)

__global__ __launch_bounds__(256, 2) void conv_edge(const int* nbr, const float* cb2, int layer) {
    __nv_bfloat16* Es  = (__nv_bfloat16*)(smem_raw + SM_ES);
    __nv_bfloat16* Hs0 = (__nv_bfloat16*)(smem_raw + SM_HS0);
    __nv_bfloat16* Bsm = (__nv_bfloat16*)(smem_raw + SM_EBS);
    int* srcs = (int*)(smem_raw + SM_EIDX);
    int* dsts = srcs + 128;

    const int tid = threadIdx.x, tile = blockIdx.x;
    const int lane = tid & 31, warp = tid >> 5;
    const int wm = warp & 3, wn = warp >> 2;   // 4 x 2 warps: M32 x N64
    const __nv_bfloat16* W1 = g_w1 + (size_t)layer * H2 * H2;  // W1_bot = rows 128..255
    const __nv_bfloat16* W2 = g_w2 + (size_t)layer * H2 * H;

    if (tid < 128) {
        int2 pr = ((const int2*)nbr)[tile * 128 + tid];
        srcs[tid] = pr.x;
        dsts[tid] = pr.y;
    }

    // E panel: e[tile*128 .. +127][0..127]
    #pragma unroll
    for (int i = 0; i < 8; i++) {
        int idx = i * 256 + tid;
        int row = idx >> 4, col = (idx & 15) << 3;
        cp16(Es + row * E_LD + col, g_e_bf + (size_t)(tile * 128 + row) * H + col);
    }
    CP_COMMIT();

    auto ldB = [&](int t) {
        const __nv_bfloat16* wt;
        int rs;
        if (t < 4) { int half = t >> 1, kt = t & 1;
                     wt = W1 + (size_t)(128 + kt * 64) * H2 + half * 128; rs = H2; }
        else       { int kt = t - 4; wt = W2 + (size_t)(kt * 64) * H;     rs = H;  }
        __nv_bfloat16* dst = Bsm + (t & 1) * (64 * EB_LD);
        #pragma unroll
        for (int i = 0; i < 4; i++) {
            int idx = i * 256 + tid;
            int row = idx >> 4, col = (idx & 15) << 3;
            cp16(dst + row * EB_LD + col, wt + (size_t)row * rs + col);
        }
    };

    ldB(0);
    CP_COMMIT();

    // -------- Phase A --------
    {
        float acc_a[2][8][4];
        #pragma unroll
        for (int mt = 0; mt < 2; mt++)
            #pragma unroll
            for (int nt = 0; nt < 8; nt++)
                #pragma unroll
                for (int j = 0; j < 4; j++) acc_a[mt][nt][j] = 0.f;

        #pragma unroll
        for (int t = 0; t < 4; t++) {
            ldB(t + 1); CP_COMMIT(); CP_WAIT(1);
            __syncthreads();

            const int kbase = (t & 1) * 64;
            const __nv_bfloat16* Bt = Bsm + (t & 1) * (64 * EB_LD);
            #pragma unroll
            for (int k16 = 0; k16 < 4; k16++) {
                uint32_t af[2][4];
                #pragma unroll
                for (int mt = 0; mt < 2; mt++)
                    ldsm_x4(af[mt], Es + (wm * 32 + mt * 16 + (lane & 15)) * E_LD
                                      + kbase + k16 * 16 + ((lane >> 4) << 3));
                uint32_t bfr[4][4];
                #pragma unroll
                for (int q = 0; q < 4; q++)
                    ldsm_x4t(bfr[q], Bt + (k16 * 16 + (lane & 15)) * EB_LD
                                       + wn * 64 + q * 16 + ((lane >> 4) << 3));
                #pragma unroll
                for (int mt = 0; mt < 2; mt++)
                    #pragma unroll
                    for (int nt = 0; nt < 8; nt++)
                        mma_bf16(acc_a[mt][nt], af[mt], bfr[nt >> 1][(nt & 1) * 2], bfr[nt >> 1][(nt & 1) * 2 + 1]);
            }

            if (t & 1) {
                const int half = t >> 1;
                if (half == 1) __syncthreads();   // all warps done reading Es before overwrite
                __nv_bfloat16* Ht = half ? Es : Hs0;
                #pragma unroll
                for (int mt = 0; mt < 2; mt++) {
                    int rloc = wm * 32 + mt * 16 + (lane >> 2);
                    int s0 = srcs[rloc], s1 = srcs[rloc + 8];
                    #pragma unroll
                    for (int nt = 0; nt < 8; nt++) {
                        int lcol = wn * 64 + nt * 8 + (lane & 3) * 2;
                        int gcol = half * 128 + lcol;
                        float2 p0 = *(const float2*)(g_p + (size_t)s0 * H2 + gcol);
                        float2 p1 = *(const float2*)(g_p + (size_t)s1 * H2 + gcol);
                        __nv_bfloat162 v01, v23;
                        v01.x = __float2bfloat16(silu(acc_a[mt][nt][0] + p0.x));
                        v01.y = __float2bfloat16(silu(acc_a[mt][nt][1] + p0.y));
                        v23.x = __float2bfloat16(silu(acc_a[mt][nt][2] + p1.x));
                        v23.y = __float2bfloat16(silu(acc_a[mt][nt][3] + p1.y));
                        *(__nv_bfloat162*)(Ht + (size_t)rloc * E_LD + lcol) = v01;
                        *(__nv_bfloat162*)(Ht + (size_t)(rloc + 8) * E_LD + lcol) = v23;
                        acc_a[mt][nt][0] = acc_a[mt][nt][1] = acc_a[mt][nt][2] = acc_a[mt][nt][3] = 0.f;
                    }
                }
            }
            __syncthreads();
        }
    }

    // -------- Phase B --------
    float acc_b[2][8][4];
    #pragma unroll
    for (int mt = 0; mt < 2; mt++)
        #pragma unroll
        for (int nt = 0; nt < 8; nt++)
            #pragma unroll
            for (int j = 0; j < 4; j++) acc_b[mt][nt][j] = 0.f;

    #pragma unroll
    for (int t = 4; t < 8; t++) {
        if (t < 7) { ldB(t + 1); CP_COMMIT(); CP_WAIT(1); }
        else       { CP_WAIT(0); }
        __syncthreads();

        const int kb = t - 4;                       // compile-time after unroll
        const __nv_bfloat16* Apan = (kb < 2) ? Hs0 : Es;
        const int kbase = (kb & 1) * 64;
        const __nv_bfloat16* Bt = Bsm + (t & 1) * (64 * EB_LD);
        #pragma unroll
        for (int k16 = 0; k16 < 4; k16++) {
            uint32_t af[2][4];
            #pragma unroll
            for (int mt = 0; mt < 2; mt++)
                ldsm_x4(af[mt], Apan + (wm * 32 + mt * 16 + (lane & 15)) * E_LD
                                  + kbase + k16 * 16 + ((lane >> 4) << 3));
            uint32_t bfr[4][4];
            #pragma unroll
            for (int q = 0; q < 4; q++)
                ldsm_x4t(bfr[q], Bt + (k16 * 16 + (lane & 15)) * EB_LD
                                   + wn * 64 + q * 16 + ((lane >> 4) << 3));
            #pragma unroll
            for (int mt = 0; mt < 2; mt++)
                #pragma unroll
                for (int nt = 0; nt < 8; nt++)
                    mma_bf16(acc_b[mt][nt], af[mt], bfr[nt >> 1][(nt & 1) * 2], bfr[nt >> 1][(nt & 1) * 2 + 1]);
        }
        __syncthreads();
    }

    // phase B epilogue: silu + bias, scatter-add by dst (R7-proven red_v2)
    const float* bp = cb2 + layer * H;
    #pragma unroll
    for (int mt = 0; mt < 2; mt++) {
        int rloc = wm * 32 + mt * 16 + (lane >> 2);
        int d0 = dsts[rloc], d1 = dsts[rloc + 8];
        #pragma unroll
        for (int nt = 0; nt < 8; nt++) {
            int col = wn * 64 + nt * 8 + (lane & 3) * 2;
            float b0 = bp[col], b1v = bp[col + 1];
            float v0 = silu(acc_b[mt][nt][0] + b0);
            float v1 = silu(acc_b[mt][nt][1] + b1v);
            float v2 = silu(acc_b[mt][nt][2] + b0);
            float v3 = silu(acc_b[mt][nt][3] + b1v);
            red_v2(g_aggr + (size_t)d0 * H + col, v0, v1);
            red_v2(g_aggr + (size_t)d1 * H + col, v2, v3);
        }
    }
}

__global__ __launch_bounds__(H) void update_kernel(const float* lng, const float* lnb, int layer) {
    int n = blockIdx.x, c = threadIdx.x;
    float cnt = g_cnt[n];
    if (cnt < 1.f) cnt = 1.f;
    int idx = n * H + c;
    float v = g_x[idx] + g_aggr[idx] / cnt;
    g_aggr[idx] = 0.f;
    float mean, var;
    ln_stats(v, mean, var);
    float y = (v - mean) * rsqrtf(var + 1e-5f) * lng[layer * H + c] + lnb[layer * H + c];
    g_x[idx] = y;
    g_x_bf[idx] = __float2bfloat16(y);
}

__global__ __launch_bounds__(H) void pool_kernel(const int* bm) {
    int n = blockIdx.x, c = threadIdx.x;
    int g = bm[n];
    atomicAdd(&g_crystal[g * H + c], g_x[n * H + c]);
    if (c == 0) atomicAdd(&g_gcnt[g], 1.f);
}

__global__ __launch_bounds__(H) void head_kernel(const float* w1, const float* b1,
                                                 const float* w2, const float* b2,
                                                 const float* w3, const float* b3, float* out) {
    __shared__ float cr[H], h1s[H], h2s[64];
    int g = blockIdx.x, c = threadIdx.x;
    float gc = g_gcnt[g];
    if (gc < 1.f) gc = 1.f;
    cr[c] = g_crystal[g * H + c] / gc;
    __syncthreads();
    float a = b1[c];
    #pragma unroll 8
    for (int k = 0; k < H; k++) a += cr[k] * w1[k * H + c];
    h1s[c] = silu(a);
    __syncthreads();
    if (c < 64) {
        float a2 = b2[c];
        #pragma unroll 8
        for (int k = 0; k < H; k++) a2 += h1s[k] * w2[k * 64 + c];
        h2s[c] = silu(a2);
    }
    __syncthreads();
    if (c < 3) {
        float a3 = b3[c];
        #pragma unroll
        for (int k = 0; k < 64; k++) a3 += h2s[k] * w3[k * 3 + c];
        out[g * 3 + c] = a3;
    }
}

// ---------------- launch ----------------
extern "C" void kernel_launch(void* const* d_in, const int* in_sizes, int n_in,
                              void* d_out, int out_size) {
    const float* atom_fea   = (const float*)d_in[0];
    const float* nbr_fea    = (const float*)d_in[1];
    const int*   nbr_idx    = (const int*)d_in[2];
    const int*   batch_map  = (const int*)d_in[3];
    const float* emb_w      = (const float*)d_in[4];
    const float* emb_b      = (const float*)d_in[5];
    const float* emb_ln_g   = (const float*)d_in[6];
    const float* emb_ln_b   = (const float*)d_in[7];
    const float* edge_w     = (const float*)d_in[8];
    const float* edge_b     = (const float*)d_in[9];
    const float* conv_w1    = (const float*)d_in[10];
    const float* conv_b1    = (const float*)d_in[11];
    const float* conv_w2    = (const float*)d_in[12];
    const float* conv_b2    = (const float*)d_in[13];
    const float* ln_g       = (const float*)d_in[14];
    const float* ln_b       = (const float*)d_in[15];
    const float* out_w1     = (const float*)d_in[16];
    const float* out_b1     = (const float*)d_in[17];
    const float* out_w2     = (const float*)d_in[18];
    const float* out_b2     = (const float*)d_in[19];
    const float* out_w3     = (const float*)d_in[20];
    const float* out_b3     = (const float*)d_in[21];
    float* out = (float*)d_out;

    cudaFuncSetAttribute(conv_p_kernel, cudaFuncAttributeMaxDynamicSharedMemorySize, P_SMEM);
    cudaFuncSetAttribute(conv_edge,     cudaFuncAttributeMaxDynamicSharedMemorySize, E_SMEM);

    zero_kernel<<<(N_GRAPHS * H + 255) / 256, 256>>>();
    prep_w<<<(L * H2 * H2 + 255) / 256, 256>>>(conv_w1, conv_w2);
    node_embed<<<N_NODES, H>>>(atom_fea, emb_w, emb_b, emb_ln_g, emb_ln_b);
    edge_embed<<<N_EDGES / 64, 64>>>(nbr_fea, edge_w, edge_b);
    cnt_kernel<<<(N_EDGES + 255) / 256, 256>>>(nbr_idx);

    for (int l = 0; l < L; l++) {
        conv_p_kernel<<<dim3((N_NODES + 127) / 128, 2), 256, P_SMEM>>>(conv_b1, l);
        conv_edge<<<N_EDGES / 128, 256, E_SMEM>>>(nbr_idx, conv_b2, l);
        update_kernel<<<N_NODES, H>>>(ln_g, ln_b, l);
    }

    pool_kernel<<<N_NODES, H>>>(batch_map);
    head_kernel<<<N_GRAPHS, H>>>(out_w1, out_b1, out_w2, out_b2, out_w3, out_b3, out);
}

// round 15
// speedup vs baseline: 1.1255x; 1.0153x over previous
#include <cuda_runtime.h>
#include <cuda_bf16.h>
#include <cstdint>

#define N_NODES 50000
#define N_EDGES 800000
#define N_GRAPHS 1024
#define H 128
#define H2 256
#define L 5

// ---------------- scratch (__device__ globals: allowed) ----------------
__device__ float          g_x[N_NODES * H];
__device__ __nv_bfloat16  g_x_bf[N_NODES * H];
__device__ __nv_bfloat16  g_e_bf[(size_t)N_EDGES * H];
__device__ float          g_p[(size_t)N_NODES * H2];   // P = x @ W1_top + b1
__device__ float          g_aggr[N_NODES * H];
__device__ float          g_cnt[N_NODES];
__device__ float          g_crystal[N_GRAPHS * H];
__device__ float          g_gcnt[N_GRAPHS];
__device__ __nv_bfloat16  g_w1[L * H2 * H2];
__device__ __nv_bfloat16  g_w2[L * H2 * H];

__device__ __forceinline__ float silu(float x) { return x / (1.f + expf(-x)); }

// ---------------- PTX helpers ----------------
__device__ __forceinline__ void ldsm_x4(uint32_t r[4], const void* p) {
    uint32_t a = (uint32_t)__cvta_generic_to_shared(p);
    asm volatile("ldmatrix.sync.aligned.m8n8.x4.shared.b16 {%0,%1,%2,%3},[%4];\n"
                 : "=r"(r[0]), "=r"(r[1]), "=r"(r[2]), "=r"(r[3]) : "r"(a));
}
__device__ __forceinline__ void ldsm_x4t(uint32_t r[4], const void* p) {
    uint32_t a = (uint32_t)__cvta_generic_to_shared(p);
    asm volatile("ldmatrix.sync.aligned.m8n8.x4.trans.shared.b16 {%0,%1,%2,%3},[%4];\n"
                 : "=r"(r[0]), "=r"(r[1]), "=r"(r[2]), "=r"(r[3]) : "r"(a));
}
__device__ __forceinline__ void mma_bf16(float d[4], const uint32_t a[4], uint32_t b0, uint32_t b1) {
    asm volatile(
        "mma.sync.aligned.m16n8k16.row.col.f32.bf16.bf16.f32 "
        "{%0,%1,%2,%3},{%4,%5,%6,%7},{%8,%9},{%0,%1,%2,%3};\n"
        : "+f"(d[0]), "+f"(d[1]), "+f"(d[2]), "+f"(d[3])
        : "r"(a[0]), "r"(a[1]), "r"(a[2]), "r"(a[3]), "r"(b0), "r"(b1));
}
__device__ __forceinline__ void mma_tf32(float d[4], const uint32_t a[4], uint32_t b0, uint32_t b1) {
    asm volatile(
        "mma.sync.aligned.m16n8k8.row.col.f32.tf32.tf32.f32 "
        "{%0,%1,%2,%3},{%4,%5,%6,%7},{%8,%9},{%0,%1,%2,%3};\n"
        : "+f"(d[0]), "+f"(d[1]), "+f"(d[2]), "+f"(d[3])
        : "r"(a[0]), "r"(a[1]), "r"(a[2]), "r"(a[3]), "r"(b0), "r"(b1));
}
__device__ __forceinline__ float cvt_tf32(float v) {
    uint32_t o;
    asm("cvt.rna.tf32.f32 %0, %1;" : "=r"(o) : "f"(v));
    return __uint_as_float(o);
}
__device__ __forceinline__ void red_v2(float* p, float a, float b) {
    asm volatile("red.global.add.v2.f32 [%0], {%1,%2};\n" :: "l"(p), "f"(a), "f"(b) : "memory");
}
__device__ __forceinline__ void cp16(void* s, const void* g) {
    uint32_t sa = (uint32_t)__cvta_generic_to_shared(s);
    asm volatile("cp.async.cg.shared.global [%0],[%1],16;\n" :: "r"(sa), "l"(g));
}
#define CP_COMMIT() asm volatile("cp.async.commit_group;\n")
#define CP_WAIT(n)  asm volatile("cp.async.wait_group %0;\n" :: "n"(n))

// ---------------- small kernels ----------------
__global__ void zero_kernel() {
    int i = blockIdx.x * 256 + threadIdx.x;
    if (i < N_NODES)      g_cnt[i] = 0.f;
    if (i < N_GRAPHS * H) g_crystal[i] = 0.f;
    if (i < N_GRAPHS)     g_gcnt[i] = 0.f;
}

__global__ void prep_w(const float* w1, const float* w2) {
    int i = blockIdx.x * 256 + threadIdx.x;
    if (i < L * H2 * H2) g_w1[i] = __float2bfloat16(w1[i]);
    if (i < L * H2 * H)  g_w2[i] = __float2bfloat16(w2[i]);
}

__device__ __forceinline__ void ln_stats(float v, float& mean, float& var) {
    __shared__ float red[8];
    int lane = threadIdx.x & 31, wid = threadIdx.x >> 5;
    float s = v;
    #pragma unroll
    for (int o = 16; o; o >>= 1) s += __shfl_xor_sync(0xffffffffu, s, o);
    if (!lane) red[wid] = s;
    __syncthreads();
    mean = (red[0] + red[1] + red[2] + red[3]) * (1.f / H);
    float d = v - mean, sq = d * d;
    #pragma unroll
    for (int o = 16; o; o >>= 1) sq += __shfl_xor_sync(0xffffffffu, sq, o);
    if (!lane) red[4 + wid] = sq;
    __syncthreads();
    var = (red[4] + red[5] + red[6] + red[7]) * (1.f / H);
}

__global__ __launch_bounds__(H) void node_embed(const float* atom, const float* w,
                                                const float* b, const float* lg, const float* lb) {
    int n = blockIdx.x, c = threadIdx.x;
    float a0 = atom[n * 4 + 0], a1 = atom[n * 4 + 1], a2 = atom[n * 4 + 2], a3 = atom[n * 4 + 3];
    float v = b[c] + a0 * w[c] + a1 * w[H + c] + a2 * w[2 * H + c] + a3 * w[3 * H + c];
    float mean, var;
    ln_stats(v, mean, var);
    float y = (v - mean) * rsqrtf(var + 1e-5f) * lg[c] + lb[c];
    y = silu(y);
    g_x[n * H + c] = y;
    g_x_bf[n * H + c] = __float2bfloat16(y);
}

extern __shared__ char smem_raw[];

// ============ edge_embed as tf32 tensor-core GEMM ============
// e = silu(nbr_fea[800000,41] @ edge_w[41,128] + b), K padded to 48.
// Block: 128 edges x 128 cols, 256 thr = 2(M) x 4(N) warps; warp M64 x N32.
// m16n8k8 tf32: per warp mt=4, nt=4, 6 K-steps.
#define EE_K   48
#define EE_ALD 52     // A smem row pitch (floats) — conflict-free
#define EE_BLD 136    // B smem row pitch (floats) — conflict-free
#define EE_SMEM ((128 * EE_ALD + EE_K * EE_BLD) * 4)

__global__ __launch_bounds__(256, 2) void edge_embed_tc(const float* nf, const float* w,
                                                        const float* bias) {
    float* Asm = (float*)smem_raw;                  // [128][EE_ALD]
    float* Bsm = Asm + 128 * EE_ALD;                // [EE_K][EE_BLD]
    const int tid = threadIdx.x;
    const int lane = tid & 31, warp = tid >> 5;
    const int wm = warp >> 2, wn = warp & 3;        // 2 x 4
    const int e0 = blockIdx.x * 128;

    // A: nbr_fea rows (fp32, 41 wide) -> tf32-rounded, pad to 48
    for (int i = tid; i < 128 * EE_K; i += 256) {
        int r = i / EE_K, k = i % EE_K;
        float v = (k < 41) ? nf[(size_t)(e0 + r) * 41 + k] : 0.f;
        Asm[r * EE_ALD + k] = cvt_tf32(v);
    }
    // B: edge_w[k][c] -> tf32-rounded, rows 41..47 zero
    for (int i = tid; i < EE_K * H; i += 256) {
        int k = i >> 7, c = i & 127;
        float v = (k < 41) ? w[k * H + c] : 0.f;
        Bsm[k * EE_BLD + c] = cvt_tf32(v);
    }
    __syncthreads();

    float acc[4][4][4];
    #pragma unroll
    for (int mt = 0; mt < 4; mt++)
        #pragma unroll
        for (int nt = 0; nt < 4; nt++)
            #pragma unroll
            for (int j = 0; j < 4; j++) acc[mt][nt][j] = 0.f;

    #pragma unroll
    for (int ks = 0; ks < 6; ks++) {
        uint32_t a[4][4];
        #pragma unroll
        for (int mt = 0; mt < 4; mt++) {
            int r0 = wm * 64 + mt * 16 + (lane >> 2);
            int c0 = ks * 8 + (lane & 3);
            a[mt][0] = __float_as_uint(Asm[r0 * EE_ALD + c0]);
            a[mt][1] = __float_as_uint(Asm[(r0 + 8) * EE_ALD + c0]);
            a[mt][2] = __float_as_uint(Asm[r0 * EE_ALD + c0 + 4]);
            a[mt][3] = __float_as_uint(Asm[(r0 + 8) * EE_ALD + c0 + 4]);
        }
        uint32_t bf[4][2];
        #pragma unroll
        for (int nt = 0; nt < 4; nt++) {
            int c = wn * 32 + nt * 8 + (lane >> 2);
            bf[nt][0] = __float_as_uint(Bsm[(ks * 8 + (lane & 3)) * EE_BLD + c]);
            bf[nt][1] = __float_as_uint(Bsm[(ks * 8 + (lane & 3) + 4) * EE_BLD + c]);
        }
        #pragma unroll
        for (int mt = 0; mt < 4; mt++)
            #pragma unroll
            for (int nt = 0; nt < 4; nt++)
                mma_tf32(acc[mt][nt], a[mt], bf[nt][0], bf[nt][1]);
    }

    // epilogue: + bias, silu, bf16 store
    #pragma unroll
    for (int mt = 0; mt < 4; mt++) {
        int r = wm * 64 + mt * 16 + (lane >> 2);
        #pragma unroll
        for (int nt = 0; nt < 4; nt++) {
            int c = wn * 32 + nt * 8 + (lane & 3) * 2;
            float b0 = bias[c], b1 = bias[c + 1];
            __nv_bfloat162 v01, v23;
            v01.x = __float2bfloat16(silu(acc[mt][nt][0] + b0));
            v01.y = __float2bfloat16(silu(acc[mt][nt][1] + b1));
            v23.x = __float2bfloat16(silu(acc[mt][nt][2] + b0));
            v23.y = __float2bfloat16(silu(acc[mt][nt][3] + b1));
            *(__nv_bfloat162*)(g_e_bf + (size_t)(e0 + r) * H + c) = v01;
            *(__nv_bfloat162*)(g_e_bf + (size_t)(e0 + r + 8) * H + c) = v23;
        }
    }
}

__global__ void cnt_kernel(const int* nbr) {
    int i = blockIdx.x * 256 + threadIdx.x;
    if (i < N_EDGES) atomicAdd(&g_cnt[nbr[2 * i + 1]], 1.f);
}

// ================= node GEMM: P = x_bf @ W1_top + b1 (fp32 out) =============
#define PAS_LD 136
#define PBS_LD 136
#define P_SMEM (128 * PAS_LD * 2 + 2 * 64 * PBS_LD * 2)

__global__ __launch_bounds__(256, 2) void conv_p_kernel(const float* cb1, int layer) {
    __nv_bfloat16* As = (__nv_bfloat16*)smem_raw;
    __nv_bfloat16* Bs = As + 128 * PAS_LD;
    const int tid = threadIdx.x;
    const int n0 = blockIdx.x * 128, nh = blockIdx.y;
    const __nv_bfloat16* W = g_w1 + (size_t)layer * H2 * H2;   // rows 0..127 = W1_top
    const int lane = tid & 31, warp = tid >> 5;
    const int wm = warp & 3, wn = warp >> 2;   // 4 x 2 warps: M32 x N64

    #pragma unroll
    for (int i = 0; i < 8; i++) {
        int idx = i * 256 + tid;
        int row = idx >> 4, col = (idx & 15) << 3;
        int nr = n0 + row; if (nr >= N_NODES) nr = 0;
        cp16(As + row * PAS_LD + col, g_x_bf + (size_t)nr * H + col);
    }
    CP_COMMIT();
    #pragma unroll
    for (int kt = 0; kt < 2; kt++) {
        #pragma unroll
        for (int i = 0; i < 4; i++) {
            int idx = i * 256 + tid;
            int row = idx >> 4, col = (idx & 15) << 3;
            cp16(Bs + kt * 64 * PBS_LD + row * PBS_LD + col,
                 W + (size_t)(kt * 64 + row) * H2 + nh * 128 + col);
        }
        CP_COMMIT();
    }

    float acc[2][8][4];
    #pragma unroll
    for (int mt = 0; mt < 2; mt++)
        #pragma unroll
        for (int nt = 0; nt < 8; nt++)
            #pragma unroll
            for (int j = 0; j < 4; j++) acc[mt][nt][j] = 0.f;

    #pragma unroll
    for (int kt = 0; kt < 2; kt++) {
        if (kt == 0) CP_WAIT(1); else CP_WAIT(0);
        __syncthreads();
        const __nv_bfloat16* Bt = Bs + kt * 64 * PBS_LD;
        #pragma unroll
        for (int k16 = 0; k16 < 4; k16++) {
            uint32_t af[2][4];
            #pragma unroll
            for (int mt = 0; mt < 2; mt++)
                ldsm_x4(af[mt], As + (wm * 32 + mt * 16 + (lane & 15)) * PAS_LD
                                  + kt * 64 + k16 * 16 + ((lane >> 4) << 3));
            uint32_t bfr[4][4];
            #pragma unroll
            for (int q = 0; q < 4; q++)
                ldsm_x4t(bfr[q], Bt + (k16 * 16 + (lane & 15)) * PBS_LD
                                   + wn * 64 + q * 16 + ((lane >> 4) << 3));
            #pragma unroll
            for (int mt = 0; mt < 2; mt++)
                #pragma unroll
                for (int nt = 0; nt < 8; nt++)
                    mma_bf16(acc[mt][nt], af[mt], bfr[nt >> 1][(nt & 1) * 2], bfr[nt >> 1][(nt & 1) * 2 + 1]);
        }
    }

    const float* bp = cb1 + layer * H2 + nh * 128;
    #pragma unroll
    for (int mt = 0; mt < 2; mt++) {
        int r = wm * 32 + mt * 16 + (lane >> 2);
        #pragma unroll
        for (int nt = 0; nt < 8; nt++) {
            int col = wn * 64 + nt * 8 + (lane & 3) * 2;
            float b0 = bp[col], b1v = bp[col + 1];
            if (n0 + r < N_NODES) {
                float2 v = {acc[mt][nt][0] + b0, acc[mt][nt][1] + b1v};
                *(float2*)(g_p + (size_t)(n0 + r) * H2 + nh * 128 + col) = v;
            }
            if (n0 + r + 8 < N_NODES) {
                float2 v = {acc[mt][nt][2] + b0, acc[mt][nt][3] + b1v};
                *(float2*)(g_p + (size_t)(n0 + r + 8) * H2 + nh * 128 + col) = v;
            }
        }
    }
}

// ================= fused edge conv, M=128, 2 CTAs/SM (R7-proven) =============
#define E_LD  136
#define EB_LD 136
#define SM_ES   0
#define SM_HS0  (128 * E_LD * 2)
#define SM_EBS  (SM_HS0 + 128 * E_LD * 2)
#define SM_EIDX (SM_EBS + 2 * 64 * EB_LD * 2)
#define E_SMEM  (SM_EIDX + 2 * 128 * 4)

__global__ __launch_bounds__(256, 2) void conv_edge(const int* nbr, const float* cb2, int layer) {
    __nv_bfloat16* Es  = (__nv_bfloat16*)(smem_raw + SM_ES);
    __nv_bfloat16* Hs0 = (__nv_bfloat16*)(smem_raw + SM_HS0);
    __nv_bfloat16* Bsm = (__nv_bfloat16*)(smem_raw + SM_EBS);
    int* srcs = (int*)(smem_raw + SM_EIDX);
    int* dsts = srcs + 128;

    const int tid = threadIdx.x, tile = blockIdx.x;
    const int lane = tid & 31, warp = tid >> 5;
    const int wm = warp & 3, wn = warp >> 2;   // 4 x 2 warps: M32 x N64
    const __nv_bfloat16* W1 = g_w1 + (size_t)layer * H2 * H2;  // W1_bot = rows 128..255
    const __nv_bfloat16* W2 = g_w2 + (size_t)layer * H2 * H;

    if (tid < 128) {
        int2 pr = ((const int2*)nbr)[tile * 128 + tid];
        srcs[tid] = pr.x;
        dsts[tid] = pr.y;
    }

    #pragma unroll
    for (int i = 0; i < 8; i++) {
        int idx = i * 256 + tid;
        int row = idx >> 4, col = (idx & 15) << 3;
        cp16(Es + row * E_LD + col, g_e_bf + (size_t)(tile * 128 + row) * H + col);
    }
    CP_COMMIT();

    auto ldB = [&](int t) {
        const __nv_bfloat16* wt;
        int rs;
        if (t < 4) { int half = t >> 1, kt = t & 1;
                     wt = W1 + (size_t)(128 + kt * 64) * H2 + half * 128; rs = H2; }
        else       { int kt = t - 4; wt = W2 + (size_t)(kt * 64) * H;     rs = H;  }
        __nv_bfloat16* dst = Bsm + (t & 1) * (64 * EB_LD);
        #pragma unroll
        for (int i = 0; i < 4; i++) {
            int idx = i * 256 + tid;
            int row = idx >> 4, col = (idx & 15) << 3;
            cp16(dst + row * EB_LD + col, wt + (size_t)row * rs + col);
        }
    };

    ldB(0);
    CP_COMMIT();

    // -------- Phase A --------
    {
        float acc_a[2][8][4];
        #pragma unroll
        for (int mt = 0; mt < 2; mt++)
            #pragma unroll
            for (int nt = 0; nt < 8; nt++)
                #pragma unroll
                for (int j = 0; j < 4; j++) acc_a[mt][nt][j] = 0.f;

        #pragma unroll
        for (int t = 0; t < 4; t++) {
            ldB(t + 1); CP_COMMIT(); CP_WAIT(1);
            __syncthreads();

            const int kbase = (t & 1) * 64;
            const __nv_bfloat16* Bt = Bsm + (t & 1) * (64 * EB_LD);
            #pragma unroll
            for (int k16 = 0; k16 < 4; k16++) {
                uint32_t af[2][4];
                #pragma unroll
                for (int mt = 0; mt < 2; mt++)
                    ldsm_x4(af[mt], Es + (wm * 32 + mt * 16 + (lane & 15)) * E_LD
                                      + kbase + k16 * 16 + ((lane >> 4) << 3));
                uint32_t bfr[4][4];
                #pragma unroll
                for (int q = 0; q < 4; q++)
                    ldsm_x4t(bfr[q], Bt + (k16 * 16 + (lane & 15)) * EB_LD
                                       + wn * 64 + q * 16 + ((lane >> 4) << 3));
                #pragma unroll
                for (int mt = 0; mt < 2; mt++)
                    #pragma unroll
                    for (int nt = 0; nt < 8; nt++)
                        mma_bf16(acc_a[mt][nt], af[mt], bfr[nt >> 1][(nt & 1) * 2], bfr[nt >> 1][(nt & 1) * 2 + 1]);
            }

            if (t & 1) {
                const int half = t >> 1;
                if (half == 1) __syncthreads();   // all warps done reading Es before overwrite
                __nv_bfloat16* Ht = half ? Es : Hs0;
                #pragma unroll
                for (int mt = 0; mt < 2; mt++) {
                    int rloc = wm * 32 + mt * 16 + (lane >> 2);
                    int s0 = srcs[rloc], s1 = srcs[rloc + 8];
                    #pragma unroll
                    for (int nt = 0; nt < 8; nt++) {
                        int lcol = wn * 64 + nt * 8 + (lane & 3) * 2;
                        int gcol = half * 128 + lcol;
                        float2 p0 = *(const float2*)(g_p + (size_t)s0 * H2 + gcol);
                        float2 p1 = *(const float2*)(g_p + (size_t)s1 * H2 + gcol);
                        __nv_bfloat162 v01, v23;
                        v01.x = __float2bfloat16(silu(acc_a[mt][nt][0] + p0.x));
                        v01.y = __float2bfloat16(silu(acc_a[mt][nt][1] + p0.y));
                        v23.x = __float2bfloat16(silu(acc_a[mt][nt][2] + p1.x));
                        v23.y = __float2bfloat16(silu(acc_a[mt][nt][3] + p1.y));
                        *(__nv_bfloat162*)(Ht + (size_t)rloc * E_LD + lcol) = v01;
                        *(__nv_bfloat162*)(Ht + (size_t)(rloc + 8) * E_LD + lcol) = v23;
                        acc_a[mt][nt][0] = acc_a[mt][nt][1] = acc_a[mt][nt][2] = acc_a[mt][nt][3] = 0.f;
                    }
                }
            }
            __syncthreads();
        }
    }

    // -------- Phase B --------
    float acc_b[2][8][4];
    #pragma unroll
    for (int mt = 0; mt < 2; mt++)
        #pragma unroll
        for (int nt = 0; nt < 8; nt++)
            #pragma unroll
            for (int j = 0; j < 4; j++) acc_b[mt][nt][j] = 0.f;

    #pragma unroll
    for (int t = 4; t < 8; t++) {
        if (t < 7) { ldB(t + 1); CP_COMMIT(); CP_WAIT(1); }
        else       { CP_WAIT(0); }
        __syncthreads();

        const int kb = t - 4;
        const __nv_bfloat16* Apan = (kb < 2) ? Hs0 : Es;
        const int kbase = (kb & 1) * 64;
        const __nv_bfloat16* Bt = Bsm + (t & 1) * (64 * EB_LD);
        #pragma unroll
        for (int k16 = 0; k16 < 4; k16++) {
            uint32_t af[2][4];
            #pragma unroll
            for (int mt = 0; mt < 2; mt++)
                ldsm_x4(af[mt], Apan + (wm * 32 + mt * 16 + (lane & 15)) * E_LD
                                  + kbase + k16 * 16 + ((lane >> 4) << 3));
            uint32_t bfr[4][4];
            #pragma unroll
            for (int q = 0; q < 4; q++)
                ldsm_x4t(bfr[q], Bt + (k16 * 16 + (lane & 15)) * EB_LD
                                   + wn * 64 + q * 16 + ((lane >> 4) << 3));
            #pragma unroll
            for (int mt = 0; mt < 2; mt++)
                #pragma unroll
                for (int nt = 0; nt < 8; nt++)
                    mma_bf16(acc_b[mt][nt], af[mt], bfr[nt >> 1][(nt & 1) * 2], bfr[nt >> 1][(nt & 1) * 2 + 1]);
        }
        __syncthreads();
    }

    const float* bp = cb2 + layer * H;
    #pragma unroll
    for (int mt = 0; mt < 2; mt++) {
        int rloc = wm * 32 + mt * 16 + (lane >> 2);
        int d0 = dsts[rloc], d1 = dsts[rloc + 8];
        #pragma unroll
        for (int nt = 0; nt < 8; nt++) {
            int col = wn * 64 + nt * 8 + (lane & 3) * 2;
            float b0 = bp[col], b1v = bp[col + 1];
            float v0 = silu(acc_b[mt][nt][0] + b0);
            float v1 = silu(acc_b[mt][nt][1] + b1v);
            float v2 = silu(acc_b[mt][nt][2] + b0);
            float v3 = silu(acc_b[mt][nt][3] + b1v);
            red_v2(g_aggr + (size_t)d0 * H + col, v0, v1);
            red_v2(g_aggr + (size_t)d1 * H + col, v2, v3);
        }
    }
}

// update: 4 nodes per block (512 thr), per-group LN reduction.
__global__ __launch_bounds__(512) void update_kernel(const float* lng, const float* lnb, int layer) {
    __shared__ float red[4][8];
    int grp = threadIdx.x >> 7;          // 0..3
    int c = threadIdx.x & 127;
    int lane = threadIdx.x & 31;
    int wig = (threadIdx.x >> 5) & 3;    // warp in group
    int n = blockIdx.x * 4 + grp;        // 50000 = 4*12500 exactly
    float cnt = g_cnt[n];
    if (cnt < 1.f) cnt = 1.f;
    int idx = n * H + c;
    float v = g_x[idx] + g_aggr[idx] / cnt;
    g_aggr[idx] = 0.f;

    float s = v;
    #pragma unroll
    for (int o = 16; o; o >>= 1) s += __shfl_xor_sync(0xffffffffu, s, o);
    if (!lane) red[grp][wig] = s;
    __syncthreads();
    float mean = (red[grp][0] + red[grp][1] + red[grp][2] + red[grp][3]) * (1.f / H);
    float d = v - mean, sq = d * d;
    #pragma unroll
    for (int o = 16; o; o >>= 1) sq += __shfl_xor_sync(0xffffffffu, sq, o);
    if (!lane) red[grp][4 + wig] = sq;
    __syncthreads();
    float var = (red[grp][4] + red[grp][5] + red[grp][6] + red[grp][7]) * (1.f / H);

    float y = (v - mean) * rsqrtf(var + 1e-5f) * lng[layer * H + c] + lnb[layer * H + c];
    g_x[idx] = y;
    g_x_bf[idx] = __float2bfloat16(y);
}

__global__ __launch_bounds__(H) void pool_kernel(const int* bm) {
    int n = blockIdx.x, c = threadIdx.x;
    int g = bm[n];
    atomicAdd(&g_crystal[g * H + c], g_x[n * H + c]);
    if (c == 0) atomicAdd(&g_gcnt[g], 1.f);
}

__global__ __launch_bounds__(H) void head_kernel(const float* w1, const float* b1,
                                                 const float* w2, const float* b2,
                                                 const float* w3, const float* b3, float* out) {
    __shared__ float cr[H], h1s[H], h2s[64];
    int g = blockIdx.x, c = threadIdx.x;
    float gc = g_gcnt[g];
    if (gc < 1.f) gc = 1.f;
    cr[c] = g_crystal[g * H + c] / gc;
    __syncthreads();
    float a = b1[c];
    #pragma unroll 8
    for (int k = 0; k < H; k++) a += cr[k] * w1[k * H + c];
    h1s[c] = silu(a);
    __syncthreads();
    if (c < 64) {
        float a2 = b2[c];
        #pragma unroll 8
        for (int k = 0; k < H; k++) a2 += h1s[k] * w2[k * 64 + c];
        h2s[c] = silu(a2);
    }
    __syncthreads();
    if (c < 3) {
        float a3 = b3[c];
        #pragma unroll
        for (int k = 0; k < 64; k++) a3 += h2s[k] * w3[k * 3 + c];
        out[g * 3 + c] = a3;
    }
}

// ---------------- launch ----------------
extern "C" void kernel_launch(void* const* d_in, const int* in_sizes, int n_in,
                              void* d_out, int out_size) {
    const float* atom_fea   = (const float*)d_in[0];
    const float* nbr_fea    = (const float*)d_in[1];
    const int*   nbr_idx    = (const int*)d_in[2];
    const int*   batch_map  = (const int*)d_in[3];
    const float* emb_w      = (const float*)d_in[4];
    const float* emb_b      = (const float*)d_in[5];
    const float* emb_ln_g   = (const float*)d_in[6];
    const float* emb_ln_b   = (const float*)d_in[7];
    const float* edge_w     = (const float*)d_in[8];
    const float* edge_b     = (const float*)d_in[9];
    const float* conv_w1    = (const float*)d_in[10];
    const float* conv_b1    = (const float*)d_in[11];
    const float* conv_w2    = (const float*)d_in[12];
    const float* conv_b2    = (const float*)d_in[13];
    const float* ln_g       = (const float*)d_in[14];
    const float* ln_b       = (const float*)d_in[15];
    const float* out_w1     = (const float*)d_in[16];
    const float* out_b1     = (const float*)d_in[17];
    const float* out_w2     = (const float*)d_in[18];
    const float* out_b2     = (const float*)d_in[19];
    const float* out_w3     = (const float*)d_in[20];
    const float* out_b3     = (const float*)d_in[21];
    float* out = (float*)d_out;

    cudaFuncSetAttribute(conv_p_kernel, cudaFuncAttributeMaxDynamicSharedMemorySize, P_SMEM);
    cudaFuncSetAttribute(conv_edge,     cudaFuncAttributeMaxDynamicSharedMemorySize, E_SMEM);
    cudaFuncSetAttribute(edge_embed_tc, cudaFuncAttributeMaxDynamicSharedMemorySize, EE_SMEM);

    zero_kernel<<<(N_GRAPHS * H + 255) / 256, 256>>>();
    prep_w<<<(L * H2 * H2 + 255) / 256, 256>>>(conv_w1, conv_w2);
    node_embed<<<N_NODES, H>>>(atom_fea, emb_w, emb_b, emb_ln_g, emb_ln_b);
    edge_embed_tc<<<N_EDGES / 128, 256, EE_SMEM>>>(nbr_fea, edge_w, edge_b);
    cnt_kernel<<<(N_EDGES + 255) / 256, 256>>>(nbr_idx);

    for (int l = 0; l < L; l++) {
        conv_p_kernel<<<dim3((N_NODES + 127) / 128, 2), 256, P_SMEM>>>(conv_b1, l);
        conv_edge<<<N_EDGES / 128, 256, E_SMEM>>>(nbr_idx, conv_b2, l);
        update_kernel<<<N_NODES / 4, 512>>>(ln_g, ln_b, l);
    }

    pool_kernel<<<N_NODES, H>>>(batch_map);
    head_kernel<<<N_GRAPHS, H>>>(out_w1, out_b1, out_w2, out_b2, out_w3, out_b3, out);
}